// round 13
// baseline (speedup 1.0000x reference)
#include <cuda_runtime.h>
#include <cuda_bf16.h>
#include <mma.h>
#include <math.h>
#include <stdint.h>
using namespace nvcuda;

#define BATCH 8
#define SEQ   2048
#define DIM   256
#define ROWS  (BATCH*SEQ)
#define LOG2E 1.4426950408889634f

__device__ __align__(16) float g_WT[4*DIM*DIM];
__device__ __align__(16) float g_loc[ROWS*DIM];
__device__ __align__(16) __nv_bfloat16 g_WTh[4*DIM*DIM], g_WTl[4*DIM*DIM];
__device__ __align__(16) __nv_bfloat16 g_Xh[ROWS*DIM], g_Xl[ROWS*DIM];
__device__ __align__(16) __nv_bfloat16 g_Qh[ROWS*DIM], g_Ql[ROWS*DIM];
__device__ __align__(16) __nv_bfloat16 g_Kh[ROWS*DIM], g_Kl[ROWS*DIM];
__device__ __align__(16) __nv_bfloat16 g_Vh[ROWS*DIM], g_Vl[ROWS*DIM];

__device__ __forceinline__ float fexp2(float x){ float y; asm("ex2.approx.ftz.f32 %0, %1;" : "=f"(y) : "f"(x)); return y; }
#define FMA4(o,a,b) do{ (o).x=fmaf((a),(b).x,(o).x); (o).y=fmaf((a),(b).y,(o).y); \
                        (o).z=fmaf((a),(b).z,(o).z); (o).w=fmaf((a),(b).w,(o).w);}while(0)

__device__ __forceinline__ uint32_t packbf(__nv_bfloat16 a, __nv_bfloat16 b){
    return (uint32_t)__bfloat16_as_ushort(a) | ((uint32_t)__bfloat16_as_ushort(b)<<16);
}
__device__ __forceinline__ void split4(float4 v, uint2& h, uint2& l){
    __nv_bfloat16 hx=__float2bfloat16(v.x), hy=__float2bfloat16(v.y), hz=__float2bfloat16(v.z), hw=__float2bfloat16(v.w);
    h.x = packbf(hx,hy); h.y = packbf(hz,hw);
    l.x = packbf(__float2bfloat16(v.x-__bfloat162float(hx)), __float2bfloat16(v.y-__bfloat162float(hy)));
    l.y = packbf(__float2bfloat16(v.z-__bfloat162float(hz)), __float2bfloat16(v.w-__bfloat162float(hw)));
}
__device__ __forceinline__ void cp16(void* s, const void* g){
    uint32_t a = (uint32_t)__cvta_generic_to_shared(s);
    asm volatile("cp.async.cg.shared.global [%0], [%1], 16;" :: "r"(a), "l"(g) : "memory");
}
#define CP_COMMIT() asm volatile("cp.async.commit_group;" ::: "memory")
#define CP_WAIT1()  asm volatile("cp.async.wait_group 1;" ::: "memory")
#define CP_WAIT0()  asm volatile("cp.async.wait_group 0;" ::: "memory")

// ---------------- weight transpose + hi/lo split ----------------
__global__ void transpose_w_kernel(const float* __restrict__ Wq, const float* __restrict__ Wk,
                                   const float* __restrict__ Wv, const float* __restrict__ Wo){
    int m = blockIdx.x;
    const float* W = (m==0)?Wq:((m==1)?Wk:((m==2)?Wv:Wo));
    float* WT = g_WT + (size_t)m*DIM*DIM;
    __nv_bfloat16* WTh = g_WTh + (size_t)m*DIM*DIM;
    __nv_bfloat16* WTl = g_WTl + (size_t)m*DIM*DIM;
    for (int idx = threadIdx.x; idx < DIM*DIM; idx += blockDim.x){
        float w = W[(idx&255)*DIM + (idx>>8)];
        WT[idx] = w;
        __nv_bfloat16 h = __float2bfloat16(w);
        WTh[idx] = h;
        WTl[idx] = __float2bfloat16(w - __bfloat162float(h));
    }
}
// ---------------- x hi/lo split ----------------
__global__ void split_x_kernel(const float* __restrict__ x){
    int idx = blockIdx.x*blockDim.x + threadIdx.x;
    float4 v = *(const float4*)(x + (size_t)idx*4);
    uint2 h,l; split4(v,h,l);
    *(uint2*)(g_Xh + (size_t)idx*4) = h;
    *(uint2*)(g_Xl + (size_t)idx*4) = l;
}

// ---------------- QKV projections: bf16-split WMMA (2 CTAs/SM) ----------------
#define XS 72
#define WS 264
#define QK_XH 0
#define QK_XL 9216
#define QK_W  18432
#define QK_WL (QK_W + 33792)
#define SMEM_QKV (QK_W + 67584)

__global__ void __launch_bounds__(256,2) qkv_wmma_kernel(
        const float* __restrict__ bq, const float* __restrict__ bk, const float* __restrict__ bv){
    extern __shared__ char smch[];
    __nv_bfloat16* Xh = (__nv_bfloat16*)(smch+QK_XH);
    __nv_bfloat16* Xl = (__nv_bfloat16*)(smch+QK_XL);
    __nv_bfloat16* Wh = (__nv_bfloat16*)(smch+QK_W);
    __nv_bfloat16* Wl = (__nv_bfloat16*)(smch+QK_WL);
    float* Of = (float*)(smch+QK_W);
    int tid = threadIdx.x, wid = tid>>5;
    int m = blockIdx.y, r0 = blockIdx.x*64;
    int mw = wid&3, np = wid>>2;
    const __nv_bfloat16* WTh = g_WTh + (size_t)m*DIM*DIM;
    const __nv_bfloat16* WTl = g_WTl + (size_t)m*DIM*DIM;

    wmma::fragment<wmma::accumulator,16,16,16,float> acc[8];
    #pragma unroll
    for (int j=0;j<8;j++) wmma::fill_fragment(acc[j], 0.f);

    for (int ck = 0; ck < 4; ++ck){
        __syncthreads();
        #pragma unroll
        for (int it=0; it<2; ++it){
            int idx = tid + it*256;
            int r = idx>>3, c8 = idx&7;
            size_t gsrc = (size_t)(r0+r)*DIM + ck*64 + c8*8;
            *(uint4*)(Xh + r*XS + c8*8) = *(const uint4*)(g_Xh + gsrc);
            *(uint4*)(Xl + r*XS + c8*8) = *(const uint4*)(g_Xl + gsrc);
        }
        #pragma unroll
        for (int it=0; it<8; ++it){
            int idx = tid + it*256;
            int dd = idx>>5, c8 = idx&31;
            size_t gsrc = (size_t)(ck*64+dd)*DIM + c8*8;
            *(uint4*)(Wh + dd*WS + c8*8) = *(const uint4*)(WTh + gsrc);
            *(uint4*)(Wl + dd*WS + c8*8) = *(const uint4*)(WTl + gsrc);
        }
        __syncthreads();
        #pragma unroll
        for (int k=0;k<4;++k){
            wmma::fragment<wmma::matrix_a,16,16,16,__nv_bfloat16,wmma::row_major> ah, al;
            wmma::load_matrix_sync(ah, Xh + mw*16*XS + k*16, XS);
            wmma::load_matrix_sync(al, Xl + mw*16*XS + k*16, XS);
            #pragma unroll
            for (int j=0;j<8;++j){
                int n0 = np*128 + j*16;
                wmma::fragment<wmma::matrix_b,16,16,16,__nv_bfloat16,wmma::row_major> bh, bl;
                wmma::load_matrix_sync(bh, Wh + k*16*WS + n0, WS);
                wmma::load_matrix_sync(bl, Wl + k*16*WS + n0, WS);
                wmma::mma_sync(acc[j], ah, bh, acc[j]);
                wmma::mma_sync(acc[j], al, bh, acc[j]);
                wmma::mma_sync(acc[j], ah, bl, acc[j]);
            }
        }
    }
    __syncthreads();
    #pragma unroll
    for (int j=0;j<8;++j)
        wmma::store_matrix_sync(Of + mw*16*WS + np*128 + j*16, acc[j], WS, wmma::mem_row_major);
    __syncthreads();

    const float* bias = (m==0)?bq:((m==1)?bk:bv);
    __nv_bfloat16* oh = (m==0)?g_Qh:((m==1)?g_Kh:g_Vh);
    __nv_bfloat16* ol = (m==0)?g_Ql:((m==1)?g_Kl:g_Vl);
    int row = tid>>2, part = tid&3;
    #pragma unroll
    for (int c4=0;c4<16;++c4){
        float4 v = *(const float4*)(Of + row*WS + part*64 + c4*4);
        float4 bb = *(const float4*)(bias + part*64 + c4*4);
        v.x+=bb.x; v.y+=bb.y; v.z+=bb.z; v.w+=bb.w;
        uint2 h,l; split4(v,h,l);
        size_t off = (size_t)(r0+row)*DIM + part*64 + c4*4;
        *(uint2*)(oh+off) = h; *(uint2*)(ol+off) = l;
    }
}

// ---------------- WMMA bf16-split flash attention: 512 threads, 16 warps ----------------
#define QS 264
#define PS 72
#define A_QH 0
#define A_QL 33792
#define A_K  67584
#define A_V  135168
#define A_SS 202752
#define A_LS 221184
#define SMEM_ATTN 221440
#define NT 512

__device__ __forceinline__ void stage64(__nv_bfloat16* s, const __nv_bfloat16* g, int tid){
    #pragma unroll
    for (int it=0; it<4; ++it){
        int idx = tid + it*NT;
        int r = idx>>5, c8 = idx&31;
        *(uint4*)(s + r*QS + c8*8) = *(const uint4*)(g + (size_t)r*DIM + c8*8);
    }
}
__device__ __forceinline__ void stage64_async(__nv_bfloat16* s, const __nv_bfloat16* g, int tid){
    #pragma unroll
    for (int it=0; it<4; ++it){
        int idx = tid + it*NT;
        int r = idx>>5, c8 = idx&31;
        cp16(s + r*QS + c8*8, g + (size_t)r*DIM + c8*8);
    }
}

__global__ void __launch_bounds__(NT,1) attn_wmma_kernel(){
    extern __shared__ char smch[];
    __nv_bfloat16* Qh = (__nv_bfloat16*)(smch+A_QH);
    __nv_bfloat16* Ql = (__nv_bfloat16*)(smch+A_QL);
    __nv_bfloat16* Kh = (__nv_bfloat16*)(smch+A_K);
    __nv_bfloat16* Kl = Kh + 64*QS;
    __nv_bfloat16* Vh = (__nv_bfloat16*)(smch+A_V);
    __nv_bfloat16* Vl = Vh + 64*QS;
    float* Of = (float*)(smch+A_K);
    float* Ss = (float*)(smch+A_SS);
    __nv_bfloat16* Ph = (__nv_bfloat16*)(smch+A_SS);
    __nv_bfloat16* Pl = (__nv_bfloat16*)(smch+A_SS+9216);
    float* lsum = (float*)(smch+A_LS);

    int tid = threadIdx.x, wid = tid>>5;
    int b = blockIdx.y, q0 = blockIdx.x*64;
    int mw = wid&3, np = wid>>2;        // 4 m-strips x 4 n-groups
    int row = tid>>3, part = tid&7;     // softmax/output mapping (64 rows x 8 parts)
    size_t bb = (size_t)b*SEQ*DIM;

    stage64_async(Kh, g_Kh + bb, tid);
    stage64_async(Kl, g_Kl + bb, tid);
    CP_COMMIT();
    stage64(Qh, g_Qh + bb + (size_t)q0*DIM, tid);
    stage64(Ql, g_Ql + bb + (size_t)q0*DIM, tid);
    if (tid < 64) lsum[tid] = 0.f;

    wmma::fragment<wmma::accumulator,16,16,16,float> o[4];
    #pragma unroll
    for (int j=0;j<4;j++) wmma::fill_fragment(o[j], 0.f);

    for (int kt = 0; kt < SEQ/64; ++kt){
        size_t kb = bb + (size_t)kt*64*DIM;
        stage64_async(Vh, g_Vh + kb, tid);
        stage64_async(Vl, g_Vl + kb, tid);
        CP_COMMIT();
        CP_WAIT1();
        __syncthreads();

        // ---- S: warp computes 16x16 block (rows mw*16, cols np*16); 3 term chains ----
        wmma::fragment<wmma::accumulator,16,16,16,float> chh, clh, chl;
        wmma::fill_fragment(chh, 0.f);
        wmma::fill_fragment(clh, 0.f);
        wmma::fill_fragment(chl, 0.f);
        #pragma unroll
        for (int k=0;k<16;++k){
            wmma::fragment<wmma::matrix_a,16,16,16,__nv_bfloat16,wmma::row_major> ah, al;
            wmma::load_matrix_sync(ah, Qh + mw*16*QS + k*16, QS);
            wmma::load_matrix_sync(al, Ql + mw*16*QS + k*16, QS);
            wmma::fragment<wmma::matrix_b,16,16,16,__nv_bfloat16,wmma::col_major> bh, bl;
            wmma::load_matrix_sync(bh, Kh + np*16*QS + k*16, QS);
            wmma::load_matrix_sync(bl, Kl + np*16*QS + k*16, QS);
            wmma::mma_sync(chh, ah, bh, chh);
            wmma::mma_sync(clh, al, bh, clh);
            wmma::mma_sync(chl, ah, bl, chl);
        }
        #pragma unroll
        for (int t=0; t<chh.num_elements; ++t)
            chh.x[t] += clh.x[t] + chl.x[t];
        wmma::store_matrix_sync(Ss + mw*16*PS + np*16, chh, PS, wmma::mem_row_major);
        __syncthreads();

        if (kt < SEQ/64-1){
            size_t kbn = kb + (size_t)64*DIM;
            stage64_async(Kh, g_Kh + kbn, tid);
            stage64_async(Kl, g_Kl + kbn, tid);
            CP_COMMIT();
        }

        // ---- softmax: 8 cols/thread; read to regs, overlay P on S buffer ----
        float sv[8];
        #pragma unroll
        for (int c2=0;c2<8;++c2) sv[c2] = Ss[row*PS + part*8 + c2];
        __syncthreads();
        {
            float psum = 0.f;
            __nv_bfloat16* phr = Ph + row*PS + part*8;
            __nv_bfloat16* plr = Pl + row*PS + part*8;
            #pragma unroll
            for (int c2=0;c2<8;++c2){
                float p = fexp2(sv[c2]*LOG2E);
                psum += p;
                __nv_bfloat16 h = __float2bfloat16(p);
                phr[c2] = h;
                plr[c2] = __float2bfloat16(p - __bfloat162float(h));
            }
            psum += __shfl_xor_sync(0xffffffffu, psum, 1);
            psum += __shfl_xor_sync(0xffffffffu, psum, 2);
            psum += __shfl_xor_sync(0xffffffffu, psum, 4);
            if (part == 0) lsum[row] += psum;
        }
        __syncthreads();

        if (kt < SEQ/64-1) { CP_WAIT1(); } else { CP_WAIT0(); }
        __syncthreads();

        // ---- PV: warp computes rows mw*16, cols np*64..+64 (4 frags) ----
        #pragma unroll
        for (int k=0;k<4;++k){
            wmma::fragment<wmma::matrix_a,16,16,16,__nv_bfloat16,wmma::row_major> ah, al;
            wmma::load_matrix_sync(ah, Ph + mw*16*PS + k*16, PS);
            wmma::load_matrix_sync(al, Pl + mw*16*PS + k*16, PS);
            #pragma unroll
            for (int j=0;j<4;++j){
                int n0 = np*64 + j*16;
                wmma::fragment<wmma::matrix_b,16,16,16,__nv_bfloat16,wmma::row_major> bh, bl;
                wmma::load_matrix_sync(bh, Vh + k*16*QS + n0, QS);
                wmma::load_matrix_sync(bl, Vl + k*16*QS + n0, QS);
                wmma::mma_sync(o[j], ah, bh, o[j]);
                wmma::mma_sync(o[j], al, bh, o[j]);
                wmma::mma_sync(o[j], ah, bl, o[j]);
            }
        }
        __syncthreads();
    }

    #pragma unroll
    for (int j=0;j<4;++j)
        wmma::store_matrix_sync(Of + mw*16*QS + np*64 + j*16, o[j], QS, wmma::mem_row_major);
    __syncthreads();
    {
        float inv = 1.0f / lsum[row];
        const float* orow = Of + row*QS + part*32;
        float* gout = g_loc + (size_t)(b*SEQ+q0+row)*DIM + part*32;
        #pragma unroll
        for (int c4=0;c4<8;++c4){
            float4 v = *(const float4*)(orow + c4*4);
            v.x*=inv; v.y*=inv; v.z*=inv; v.w*=inv;
            *(float4*)(gout + c4*4) = v;
        }
    }
}

// ---------------- fp32 64x256 GEMM mainloop (proj) ----------------
__device__ __forceinline__ void gemm64x256(const float* __restrict__ A, int r0, const float* __restrict__ WT,
                                           float* Xs, float* WsT, int tx, int ty, int tid, float4 acc[4][4]){
    for (int dc = 0; dc < 8; ++dc){
        #pragma unroll
        for (int it = 0; it < 2; ++it){
            int idx = tid + it*256; int r = idx>>3, d4 = idx&7;
            float4 v = *(const float4*)(A + (size_t)(r0+r)*DIM + dc*32 + d4*4);
            float* p = &Xs[r*33 + d4*4]; p[0]=v.x; p[1]=v.y; p[2]=v.z; p[3]=v.w;
        }
        #pragma unroll
        for (int it = 0; it < 8; ++it){
            int idx = tid + it*256; int dd = idx>>6, c4 = idx&63;
            *(float4*)&WsT[dd*256 + c4*4] = *(const float4*)(WT + (size_t)(dc*32+dd)*DIM + c4*4);
        }
        __syncthreads();
        #pragma unroll 8
        for (int dd = 0; dd < 32; ++dd){
            float a[4];
            #pragma unroll
            for (int i = 0; i < 4; ++i) a[i] = Xs[(4*ty+i)*33 + dd];
            #pragma unroll
            for (int j = 0; j < 4; ++j){
                float4 b = *(float4*)&WsT[dd*256 + 4*tx + 64*j];
                #pragma unroll
                for (int i = 0; i < 4; ++i) FMA4(acc[i][j], a[i], b);
            }
        }
        __syncthreads();
    }
}

// ---------------- output projection + LayerNorm + LeakyReLU ----------------
__global__ __launch_bounds__(256) void proj_ln_kernel(const float* __restrict__ bo,
        const float* __restrict__ gamma, const float* __restrict__ beta, float* __restrict__ out){
    __shared__ float Xs[64*33];
    __shared__ float WsT[32*256];
    const float* WT = g_WT + (size_t)3*DIM*DIM;
    int r0 = blockIdx.x*64;
    int tid = threadIdx.x, tx = tid&15, ty = tid>>4;
    float4 acc[4][4];
    #pragma unroll
    for (int i=0;i<4;i++){ acc[i][0]=acc[i][1]=acc[i][2]=acc[i][3]=make_float4(0.f,0.f,0.f,0.f); }
    gemm64x256(g_loc, r0, WT, Xs, WsT, tx, ty, tid, acc);
    #pragma unroll
    for (int j=0;j<4;j++){
        float4 bbv = *(const float4*)(bo + 4*tx + 64*j);
        #pragma unroll
        for (int i=0;i<4;i++){ acc[i][j].x+=bbv.x; acc[i][j].y+=bbv.y; acc[i][j].z+=bbv.z; acc[i][j].w+=bbv.w; }
    }
    #pragma unroll
    for (int i=0;i<4;i++){
        float ssum = 0.f;
        #pragma unroll
        for (int j=0;j<4;j++) ssum += acc[i][j].x + acc[i][j].y + acc[i][j].z + acc[i][j].w;
        #pragma unroll
        for (int off=8; off>=1; off>>=1) ssum += __shfl_xor_sync(0xffffffffu, ssum, off);
        float mu = ssum * (1.0f/DIM);
        float vsum = 0.f;
        #pragma unroll
        for (int j=0;j<4;j++){
            float dx=acc[i][j].x-mu, dy=acc[i][j].y-mu, dz=acc[i][j].z-mu, dw=acc[i][j].w-mu;
            vsum += dx*dx + dy*dy + dz*dz + dw*dw;
        }
        #pragma unroll
        for (int off=8; off>=1; off>>=1) vsum += __shfl_xor_sync(0xffffffffu, vsum, off);
        float rstd = rsqrtf(vsum*(1.0f/DIM) + 1e-5f);
        #pragma unroll
        for (int j=0;j<4;j++){
            float4 g  = *(const float4*)(gamma + 4*tx + 64*j);
            float4 bt = *(const float4*)(beta  + 4*tx + 64*j);
            float4 h  = acc[i][j]; float4 y;
            y.x=(h.x-mu)*rstd*g.x+bt.x; y.x=(y.x>=0.f)?y.x:0.01f*y.x;
            y.y=(h.y-mu)*rstd*g.y+bt.y; y.y=(y.y>=0.f)?y.y:0.01f*y.y;
            y.z=(h.z-mu)*rstd*g.z+bt.z; y.z=(y.z>=0.f)?y.z:0.01f*y.z;
            y.w=(h.w-mu)*rstd*g.w+bt.w; y.w=(y.w>=0.f)?y.w:0.01f*y.w;
            *(float4*)(out + (size_t)(r0+4*ty+i)*DIM + 4*tx + 64*j) = y;
        }
    }
}

// ---------------- entry ----------------
extern "C" void kernel_launch(void* const* d_in, const int* in_sizes, int n_in,
                              void* d_out, int out_size){
    const float* x     = (const float*)d_in[0];
    const float* bq    = (const float*)d_in[2];
    const float* bk    = (const float*)d_in[4];
    const float* bv    = (const float*)d_in[6];
    const float* bo    = (const float*)d_in[8];
    const float* gamma = (const float*)d_in[9];
    const float* beta  = (const float*)d_in[10];
    float* out = (float*)d_out;

    cudaFuncSetAttribute(qkv_wmma_kernel, cudaFuncAttributeMaxDynamicSharedMemorySize, SMEM_QKV);
    cudaFuncSetAttribute(attn_wmma_kernel, cudaFuncAttributeMaxDynamicSharedMemorySize, SMEM_ATTN);

    transpose_w_kernel<<<4, 256>>>((const float*)d_in[1], (const float*)d_in[3],
                                   (const float*)d_in[5], (const float*)d_in[7]);
    split_x_kernel<<<ROWS*DIM/4/256, 256>>>(x);
    qkv_wmma_kernel<<<dim3(ROWS/64, 3), 256, SMEM_QKV>>>(bq, bk, bv);
    attn_wmma_kernel<<<dim3(SEQ/64, BATCH), NT, SMEM_ATTN>>>();
    proj_ln_kernel<<<ROWS/64, 256>>>(bo, gamma, beta, out);
}

// round 14
// speedup vs baseline: 1.0026x; 1.0026x over previous
#include <cuda_runtime.h>
#include <cuda_bf16.h>
#include <mma.h>
#include <math.h>
#include <stdint.h>
using namespace nvcuda;

#define BATCH 8
#define SEQ   2048
#define DIM   256
#define ROWS  (BATCH*SEQ)
#define LOG2E 1.4426950408889634f

__device__ __align__(16) float g_WT[4*DIM*DIM];
__device__ __align__(16) float g_loc[ROWS*DIM];
__device__ __align__(16) __nv_bfloat16 g_WTh[4*DIM*DIM], g_WTl[4*DIM*DIM];
__device__ __align__(16) __nv_bfloat16 g_Xh[ROWS*DIM], g_Xl[ROWS*DIM];
__device__ __align__(16) __nv_bfloat16 g_Qh[ROWS*DIM], g_Ql[ROWS*DIM];
__device__ __align__(16) __nv_bfloat16 g_Kh[ROWS*DIM], g_Kl[ROWS*DIM];
__device__ __align__(16) __nv_bfloat16 g_Vh[ROWS*DIM], g_Vl[ROWS*DIM];

__device__ __forceinline__ float fexp2(float x){ float y; asm("ex2.approx.ftz.f32 %0, %1;" : "=f"(y) : "f"(x)); return y; }
#define FMA4(o,a,b) do{ (o).x=fmaf((a),(b).x,(o).x); (o).y=fmaf((a),(b).y,(o).y); \
                        (o).z=fmaf((a),(b).z,(o).z); (o).w=fmaf((a),(b).w,(o).w);}while(0)

__device__ __forceinline__ uint32_t packbf(__nv_bfloat16 a, __nv_bfloat16 b){
    return (uint32_t)__bfloat16_as_ushort(a) | ((uint32_t)__bfloat16_as_ushort(b)<<16);
}
__device__ __forceinline__ void split4(float4 v, uint2& h, uint2& l){
    __nv_bfloat16 hx=__float2bfloat16(v.x), hy=__float2bfloat16(v.y), hz=__float2bfloat16(v.z), hw=__float2bfloat16(v.w);
    h.x = packbf(hx,hy); h.y = packbf(hz,hw);
    l.x = packbf(__float2bfloat16(v.x-__bfloat162float(hx)), __float2bfloat16(v.y-__bfloat162float(hy)));
    l.y = packbf(__float2bfloat16(v.z-__bfloat162float(hz)), __float2bfloat16(v.w-__bfloat162float(hw)));
}
__device__ __forceinline__ void cp16(void* s, const void* g){
    uint32_t a = (uint32_t)__cvta_generic_to_shared(s);
    asm volatile("cp.async.cg.shared.global [%0], [%1], 16;" :: "r"(a), "l"(g) : "memory");
}
#define CP_COMMIT() asm volatile("cp.async.commit_group;" ::: "memory")
#define CP_WAIT1()  asm volatile("cp.async.wait_group 1;" ::: "memory")
#define CP_WAIT0()  asm volatile("cp.async.wait_group 0;" ::: "memory")

// ---------------- weight transpose + hi/lo split ----------------
__global__ void transpose_w_kernel(const float* __restrict__ Wq, const float* __restrict__ Wk,
                                   const float* __restrict__ Wv, const float* __restrict__ Wo){
    int m = blockIdx.x;
    const float* W = (m==0)?Wq:((m==1)?Wk:((m==2)?Wv:Wo));
    float* WT = g_WT + (size_t)m*DIM*DIM;
    __nv_bfloat16* WTh = g_WTh + (size_t)m*DIM*DIM;
    __nv_bfloat16* WTl = g_WTl + (size_t)m*DIM*DIM;
    for (int idx = threadIdx.x; idx < DIM*DIM; idx += blockDim.x){
        float w = W[(idx&255)*DIM + (idx>>8)];
        WT[idx] = w;
        __nv_bfloat16 h = __float2bfloat16(w);
        WTh[idx] = h;
        WTl[idx] = __float2bfloat16(w - __bfloat162float(h));
    }
}
// ---------------- x hi/lo split ----------------
__global__ void split_x_kernel(const float* __restrict__ x){
    int idx = blockIdx.x*blockDim.x + threadIdx.x;
    float4 v = *(const float4*)(x + (size_t)idx*4);
    uint2 h,l; split4(v,h,l);
    *(uint2*)(g_Xh + (size_t)idx*4) = h;
    *(uint2*)(g_Xl + (size_t)idx*4) = l;
}

// ---------------- QKV projections: bf16-split WMMA (2 CTAs/SM) ----------------
#define XS 72
#define WS 264
#define QK_XH 0
#define QK_XL 9216
#define QK_W  18432
#define QK_WL (QK_W + 33792)
#define SMEM_QKV (QK_W + 67584)

__global__ void __launch_bounds__(256,2) qkv_wmma_kernel(
        const float* __restrict__ bq, const float* __restrict__ bk, const float* __restrict__ bv){
    extern __shared__ char smch[];
    __nv_bfloat16* Xh = (__nv_bfloat16*)(smch+QK_XH);
    __nv_bfloat16* Xl = (__nv_bfloat16*)(smch+QK_XL);
    __nv_bfloat16* Wh = (__nv_bfloat16*)(smch+QK_W);
    __nv_bfloat16* Wl = (__nv_bfloat16*)(smch+QK_WL);
    float* Of = (float*)(smch+QK_W);
    int tid = threadIdx.x, wid = tid>>5;
    int m = blockIdx.y, r0 = blockIdx.x*64;
    int mw = wid&3, np = wid>>2;
    const __nv_bfloat16* WTh = g_WTh + (size_t)m*DIM*DIM;
    const __nv_bfloat16* WTl = g_WTl + (size_t)m*DIM*DIM;

    wmma::fragment<wmma::accumulator,16,16,16,float> acc[8];
    #pragma unroll
    for (int j=0;j<8;j++) wmma::fill_fragment(acc[j], 0.f);

    for (int ck = 0; ck < 4; ++ck){
        __syncthreads();
        #pragma unroll
        for (int it=0; it<2; ++it){
            int idx = tid + it*256;
            int r = idx>>3, c8 = idx&7;
            size_t gsrc = (size_t)(r0+r)*DIM + ck*64 + c8*8;
            *(uint4*)(Xh + r*XS + c8*8) = *(const uint4*)(g_Xh + gsrc);
            *(uint4*)(Xl + r*XS + c8*8) = *(const uint4*)(g_Xl + gsrc);
        }
        #pragma unroll
        for (int it=0; it<8; ++it){
            int idx = tid + it*256;
            int dd = idx>>5, c8 = idx&31;
            size_t gsrc = (size_t)(ck*64+dd)*DIM + c8*8;
            *(uint4*)(Wh + dd*WS + c8*8) = *(const uint4*)(WTh + gsrc);
            *(uint4*)(Wl + dd*WS + c8*8) = *(const uint4*)(WTl + gsrc);
        }
        __syncthreads();
        #pragma unroll
        for (int k=0;k<4;++k){
            wmma::fragment<wmma::matrix_a,16,16,16,__nv_bfloat16,wmma::row_major> ah, al;
            wmma::load_matrix_sync(ah, Xh + mw*16*XS + k*16, XS);
            wmma::load_matrix_sync(al, Xl + mw*16*XS + k*16, XS);
            #pragma unroll
            for (int j=0;j<8;++j){
                int n0 = np*128 + j*16;
                wmma::fragment<wmma::matrix_b,16,16,16,__nv_bfloat16,wmma::row_major> bh, bl;
                wmma::load_matrix_sync(bh, Wh + k*16*WS + n0, WS);
                wmma::load_matrix_sync(bl, Wl + k*16*WS + n0, WS);
                wmma::mma_sync(acc[j], ah, bh, acc[j]);
                wmma::mma_sync(acc[j], al, bh, acc[j]);
                wmma::mma_sync(acc[j], ah, bl, acc[j]);
            }
        }
    }
    __syncthreads();
    #pragma unroll
    for (int j=0;j<8;++j)
        wmma::store_matrix_sync(Of + mw*16*WS + np*128 + j*16, acc[j], WS, wmma::mem_row_major);
    __syncthreads();

    const float* bias = (m==0)?bq:((m==1)?bk:bv);
    __nv_bfloat16* oh = (m==0)?g_Qh:((m==1)?g_Kh:g_Vh);
    __nv_bfloat16* ol = (m==0)?g_Ql:((m==1)?g_Kl:g_Vl);
    int row = tid>>2, part = tid&3;
    #pragma unroll
    for (int c4=0;c4<16;++c4){
        float4 v = *(const float4*)(Of + row*WS + part*64 + c4*4);
        float4 bb = *(const float4*)(bias + part*64 + c4*4);
        v.x+=bb.x; v.y+=bb.y; v.z+=bb.z; v.w+=bb.w;
        uint2 h,l; split4(v,h,l);
        size_t off = (size_t)(r0+row)*DIM + part*64 + c4*4;
        *(uint2*)(oh+off) = h; *(uint2*)(ol+off) = l;
    }
}

// ---------------- WMMA bf16-split flash attention: merged S+PV phase ----------------
// q-tile 64, k-tile 32, K/V double-buffered, 256 threads.
#define QS  264
#define PS2 40
#define KBUF 16896                 // one 32x264 bf16 buffer
#define A_QH 0
#define A_QL 33792
#define A_K  67584                 // Kh[2]  (O f32 overlays K region at end)
#define A_KL 101376                // Kl[2]
#define A_V  135168                // Vh[2]
#define A_VL 168960                // Vl[2]
#define A_SS 202752                // f32 S 64x40
#define A_PH 212992
#define A_PL 218112
#define A_LS 223232
#define SMEM_ATTN 223488

__device__ __forceinline__ void stage64(__nv_bfloat16* s, const __nv_bfloat16* g, int tid){
    #pragma unroll
    for (int it=0; it<8; ++it){
        int idx = tid + it*256;
        int r = idx>>5, c8 = idx&31;
        *(uint4*)(s + r*QS + c8*8) = *(const uint4*)(g + (size_t)r*DIM + c8*8);
    }
}
__device__ __forceinline__ void stage32_async(__nv_bfloat16* s, const __nv_bfloat16* g, int tid){
    #pragma unroll
    for (int it=0; it<4; ++it){
        int idx = tid + it*256;
        int r = idx>>5, c8 = idx&31;
        cp16(s + r*QS + c8*8, g + (size_t)r*DIM + c8*8);
    }
}

__global__ void __launch_bounds__(256,1) attn_wmma_kernel(){
    extern __shared__ char smch[];
    __nv_bfloat16* Qh = (__nv_bfloat16*)(smch+A_QH);
    __nv_bfloat16* Ql = (__nv_bfloat16*)(smch+A_QL);
    float* Of = (float*)(smch+A_K);
    float* Ss = (float*)(smch+A_SS);
    __nv_bfloat16* Ph = (__nv_bfloat16*)(smch+A_PH);
    __nv_bfloat16* Pl = (__nv_bfloat16*)(smch+A_PL);
    float* lsum = (float*)(smch+A_LS);

    int tid = threadIdx.x, wid = tid>>5;
    int b = blockIdx.y, q0 = blockIdx.x*64;
    int mw = wid&3, np = wid>>2;       // 4 m-strips x 2 n-halves
    int row = tid>>2, part = tid&3;
    size_t bb = (size_t)b*SEQ*DIM;

    // S tile: warp computes S[mw*16..+16, np*16..+16] with 3 split-term chains
    auto s_tile = [&](const __nv_bfloat16* KhB, const __nv_bfloat16* KlB){
        wmma::fragment<wmma::accumulator,16,16,16,float> chh, clh, chl;
        wmma::fill_fragment(chh, 0.f);
        wmma::fill_fragment(clh, 0.f);
        wmma::fill_fragment(chl, 0.f);
        #pragma unroll
        for (int k=0;k<16;++k){
            wmma::fragment<wmma::matrix_a,16,16,16,__nv_bfloat16,wmma::row_major> ah, al;
            wmma::load_matrix_sync(ah, Qh + mw*16*QS + k*16, QS);
            wmma::load_matrix_sync(al, Ql + mw*16*QS + k*16, QS);
            wmma::fragment<wmma::matrix_b,16,16,16,__nv_bfloat16,wmma::col_major> bh, bl;
            wmma::load_matrix_sync(bh, KhB + np*16*QS + k*16, QS);
            wmma::load_matrix_sync(bl, KlB + np*16*QS + k*16, QS);
            wmma::mma_sync(chh, ah, bh, chh);
            wmma::mma_sync(clh, al, bh, clh);
            wmma::mma_sync(chl, ah, bl, chl);
        }
        #pragma unroll
        for (int t=0; t<chh.num_elements; ++t)
            chh.x[t] += clh.x[t] + chl.x[t];
        wmma::store_matrix_sync(Ss + mw*16*PS2 + np*16, chh, PS2, wmma::mem_row_major);
    };

    // prologue: K0 -> K[0];  V0 -> V[0], K1 -> K[1];  Q (sync loads)
    stage32_async((__nv_bfloat16*)(smch+A_K),            g_Kh + bb, tid);
    stage32_async((__nv_bfloat16*)(smch+A_KL),           g_Kl + bb, tid);
    CP_COMMIT();                                                     // g0
    stage32_async((__nv_bfloat16*)(smch+A_V),            g_Vh + bb, tid);
    stage32_async((__nv_bfloat16*)(smch+A_VL),           g_Vl + bb, tid);
    stage32_async((__nv_bfloat16*)(smch+A_K)+KBUF/2,     g_Kh + bb + 32*DIM, tid);
    stage32_async((__nv_bfloat16*)(smch+A_KL)+KBUF/2,    g_Kl + bb + 32*DIM, tid);
    CP_COMMIT();                                                     // g1
    stage64(Qh, g_Qh + bb + (size_t)q0*DIM, tid);
    stage64(Ql, g_Ql + bb + (size_t)q0*DIM, tid);
    if (tid < 64) lsum[tid] = 0.f;
    CP_WAIT1();
    __syncthreads();
    s_tile((__nv_bfloat16*)(smch+A_K), (__nv_bfloat16*)(smch+A_KL));  // S(0)
    __syncthreads();

    wmma::fragment<wmma::accumulator,16,16,16,float> o[8];
    #pragma unroll
    for (int j=0;j<8;j++) wmma::fill_fragment(o[j], 0.f);

    const int NIT = SEQ/32;     // 64
    for (int kt = 0; kt < NIT; ++kt){
        // ---- softmax(kt): Ss -> Ph/Pl + lsum ----
        {
            const float4* s4 = (const float4*)(Ss + row*PS2 + part*8);
            float4 v0 = s4[0], v1 = s4[1];
            float p0 = fexp2(v0.x*LOG2E), p1 = fexp2(v0.y*LOG2E);
            float p2 = fexp2(v0.z*LOG2E), p3 = fexp2(v0.w*LOG2E);
            float p4 = fexp2(v1.x*LOG2E), p5 = fexp2(v1.y*LOG2E);
            float p6 = fexp2(v1.z*LOG2E), p7 = fexp2(v1.w*LOG2E);
            float psum = ((p0+p1)+(p2+p3)) + ((p4+p5)+(p6+p7));
            __nv_bfloat16 h0=__float2bfloat16(p0), h1=__float2bfloat16(p1),
                          h2=__float2bfloat16(p2), h3=__float2bfloat16(p3),
                          h4=__float2bfloat16(p4), h5=__float2bfloat16(p5),
                          h6=__float2bfloat16(p6), h7=__float2bfloat16(p7);
            uint4 hh, ll;
            hh.x = packbf(h0,h1); hh.y = packbf(h2,h3); hh.z = packbf(h4,h5); hh.w = packbf(h6,h7);
            ll.x = packbf(__float2bfloat16(p0-__bfloat162float(h0)), __float2bfloat16(p1-__bfloat162float(h1)));
            ll.y = packbf(__float2bfloat16(p2-__bfloat162float(h2)), __float2bfloat16(p3-__bfloat162float(h3)));
            ll.z = packbf(__float2bfloat16(p4-__bfloat162float(h4)), __float2bfloat16(p5-__bfloat162float(h5)));
            ll.w = packbf(__float2bfloat16(p6-__bfloat162float(h6)), __float2bfloat16(p7-__bfloat162float(h7)));
            *(uint4*)(Ph + row*PS2 + part*8) = hh;
            *(uint4*)(Pl + row*PS2 + part*8) = ll;
            psum += __shfl_xor_sync(0xffffffffu, psum, 1);
            psum += __shfl_xor_sync(0xffffffffu, psum, 2);
            if (part == 0) lsum[row] += psum;
        }
        // ---- issue prefetches: V(kt+1) -> V[(kt+1)&1], K(kt+2) -> K[kt&1] ----
        if (kt+1 < NIT){
            int bsel = (kt+1)&1;
            stage32_async((__nv_bfloat16*)(smch+A_V)  + bsel*(KBUF/2), g_Vh + bb + (size_t)(kt+1)*32*DIM, tid);
            stage32_async((__nv_bfloat16*)(smch+A_VL) + bsel*(KBUF/2), g_Vl + bb + (size_t)(kt+1)*32*DIM, tid);
        }
        if (kt+2 < NIT){
            int bsel = kt&1;
            stage32_async((__nv_bfloat16*)(smch+A_K)  + bsel*(KBUF/2), g_Kh + bb + (size_t)(kt+2)*32*DIM, tid);
            stage32_async((__nv_bfloat16*)(smch+A_KL) + bsel*(KBUF/2), g_Kl + bb + (size_t)(kt+2)*32*DIM, tid);
        }
        CP_COMMIT();
        CP_WAIT1();                    // V(kt), K(kt+1) arrived
        __syncthreads();

        // ---- merged MMA phase: S(kt+1) then PV(kt) ----
        if (kt+1 < NIT){
            int bsel = (kt+1)&1;
            s_tile((__nv_bfloat16*)(smch+A_K)  + bsel*(KBUF/2),
                   (__nv_bfloat16*)(smch+A_KL) + bsel*(KBUF/2));
        }
        {
            int bsel = kt&1;
            const __nv_bfloat16* Vhb = (__nv_bfloat16*)(smch+A_V)  + bsel*(KBUF/2);
            const __nv_bfloat16* Vlb = (__nv_bfloat16*)(smch+A_VL) + bsel*(KBUF/2);
            #pragma unroll
            for (int k=0;k<2;++k){
                wmma::fragment<wmma::matrix_a,16,16,16,__nv_bfloat16,wmma::row_major> ah, al;
                wmma::load_matrix_sync(ah, Ph + mw*16*PS2 + k*16, PS2);
                wmma::load_matrix_sync(al, Pl + mw*16*PS2 + k*16, PS2);
                #pragma unroll
                for (int j=0;j<8;++j){
                    int n0 = np*128 + j*16;
                    wmma::fragment<wmma::matrix_b,16,16,16,__nv_bfloat16,wmma::row_major> bh, bl;
                    wmma::load_matrix_sync(bh, Vhb + k*16*QS + n0, QS);
                    wmma::load_matrix_sync(bl, Vlb + k*16*QS + n0, QS);
                    wmma::mma_sync(o[j], ah, bh, o[j]);
                    wmma::mma_sync(o[j], al, bh, o[j]);
                    wmma::mma_sync(o[j], ah, bl, o[j]);
                }
            }
        }
        __syncthreads();
    }

    // epilogue: O overlays the K region
    #pragma unroll
    for (int j=0;j<8;++j)
        wmma::store_matrix_sync(Of + mw*16*QS + np*128 + j*16, o[j], QS, wmma::mem_row_major);
    __syncthreads();
    {
        float inv = 1.0f / lsum[row];
        const float* orow = Of + row*QS + part*64;
        float* gout = g_loc + (size_t)(b*SEQ+q0+row)*DIM + part*64;
        #pragma unroll
        for (int c4=0;c4<16;++c4){
            float4 v = *(const float4*)(orow + c4*4);
            v.x*=inv; v.y*=inv; v.z*=inv; v.w*=inv;
            *(float4*)(gout + c4*4) = v;
        }
    }
}

// ---------------- fp32 64x256 GEMM mainloop (proj) ----------------
__device__ __forceinline__ void gemm64x256(const float* __restrict__ A, int r0, const float* __restrict__ WT,
                                           float* Xs, float* WsT, int tx, int ty, int tid, float4 acc[4][4]){
    for (int dc = 0; dc < 8; ++dc){
        #pragma unroll
        for (int it = 0; it < 2; ++it){
            int idx = tid + it*256; int r = idx>>3, d4 = idx&7;
            float4 v = *(const float4*)(A + (size_t)(r0+r)*DIM + dc*32 + d4*4);
            float* p = &Xs[r*33 + d4*4]; p[0]=v.x; p[1]=v.y; p[2]=v.z; p[3]=v.w;
        }
        #pragma unroll
        for (int it = 0; it < 8; ++it){
            int idx = tid + it*256; int dd = idx>>6, c4 = idx&63;
            *(float4*)&WsT[dd*256 + c4*4] = *(const float4*)(WT + (size_t)(dc*32+dd)*DIM + c4*4);
        }
        __syncthreads();
        #pragma unroll 8
        for (int dd = 0; dd < 32; ++dd){
            float a[4];
            #pragma unroll
            for (int i = 0; i < 4; ++i) a[i] = Xs[(4*ty+i)*33 + dd];
            #pragma unroll
            for (int j = 0; j < 4; ++j){
                float4 b = *(float4*)&WsT[dd*256 + 4*tx + 64*j];
                #pragma unroll
                for (int i = 0; i < 4; ++i) FMA4(acc[i][j], a[i], b);
            }
        }
        __syncthreads();
    }
}

// ---------------- output projection + LayerNorm + LeakyReLU ----------------
__global__ __launch_bounds__(256) void proj_ln_kernel(const float* __restrict__ bo,
        const float* __restrict__ gamma, const float* __restrict__ beta, float* __restrict__ out){
    __shared__ float Xs[64*33];
    __shared__ float WsT[32*256];
    const float* WT = g_WT + (size_t)3*DIM*DIM;
    int r0 = blockIdx.x*64;
    int tid = threadIdx.x, tx = tid&15, ty = tid>>4;
    float4 acc[4][4];
    #pragma unroll
    for (int i=0;i<4;i++){ acc[i][0]=acc[i][1]=acc[i][2]=acc[i][3]=make_float4(0.f,0.f,0.f,0.f); }
    gemm64x256(g_loc, r0, WT, Xs, WsT, tx, ty, tid, acc);
    #pragma unroll
    for (int j=0;j<4;j++){
        float4 bbv = *(const float4*)(bo + 4*tx + 64*j);
        #pragma unroll
        for (int i=0;i<4;i++){ acc[i][j].x+=bbv.x; acc[i][j].y+=bbv.y; acc[i][j].z+=bbv.z; acc[i][j].w+=bbv.w; }
    }
    #pragma unroll
    for (int i=0;i<4;i++){
        float ssum = 0.f;
        #pragma unroll
        for (int j=0;j<4;j++) ssum += acc[i][j].x + acc[i][j].y + acc[i][j].z + acc[i][j].w;
        #pragma unroll
        for (int off=8; off>=1; off>>=1) ssum += __shfl_xor_sync(0xffffffffu, ssum, off);
        float mu = ssum * (1.0f/DIM);
        float vsum = 0.f;
        #pragma unroll
        for (int j=0;j<4;j++){
            float dx=acc[i][j].x-mu, dy=acc[i][j].y-mu, dz=acc[i][j].z-mu, dw=acc[i][j].w-mu;
            vsum += dx*dx + dy*dy + dz*dz + dw*dw;
        }
        #pragma unroll
        for (int off=8; off>=1; off>>=1) vsum += __shfl_xor_sync(0xffffffffu, vsum, off);
        float rstd = rsqrtf(vsum*(1.0f/DIM) + 1e-5f);
        #pragma unroll
        for (int j=0;j<4;j++){
            float4 g  = *(const float4*)(gamma + 4*tx + 64*j);
            float4 bt = *(const float4*)(beta  + 4*tx + 64*j);
            float4 h  = acc[i][j]; float4 y;
            y.x=(h.x-mu)*rstd*g.x+bt.x; y.x=(y.x>=0.f)?y.x:0.01f*y.x;
            y.y=(h.y-mu)*rstd*g.y+bt.y; y.y=(y.y>=0.f)?y.y:0.01f*y.y;
            y.z=(h.z-mu)*rstd*g.z+bt.z; y.z=(y.z>=0.f)?y.z:0.01f*y.z;
            y.w=(h.w-mu)*rstd*g.w+bt.w; y.w=(y.w>=0.f)?y.w:0.01f*y.w;
            *(float4*)(out + (size_t)(r0+4*ty+i)*DIM + 4*tx + 64*j) = y;
        }
    }
}

// ---------------- entry ----------------
extern "C" void kernel_launch(void* const* d_in, const int* in_sizes, int n_in,
                              void* d_out, int out_size){
    const float* x     = (const float*)d_in[0];
    const float* bq    = (const float*)d_in[2];
    const float* bk    = (const float*)d_in[4];
    const float* bv    = (const float*)d_in[6];
    const float* bo    = (const float*)d_in[8];
    const float* gamma = (const float*)d_in[9];
    const float* beta  = (const float*)d_in[10];
    float* out = (float*)d_out;

    cudaFuncSetAttribute(qkv_wmma_kernel, cudaFuncAttributeMaxDynamicSharedMemorySize, SMEM_QKV);
    cudaFuncSetAttribute(attn_wmma_kernel, cudaFuncAttributeMaxDynamicSharedMemorySize, SMEM_ATTN);

    transpose_w_kernel<<<4, 256>>>((const float*)d_in[1], (const float*)d_in[3],
                                   (const float*)d_in[5], (const float*)d_in[7]);
    split_x_kernel<<<ROWS*DIM/4/256, 256>>>(x);
    qkv_wmma_kernel<<<dim3(ROWS/64, 3), 256, SMEM_QKV>>>(bq, bk, bv);
    attn_wmma_kernel<<<dim3(SEQ/64, BATCH), 256, SMEM_ATTN>>>();
    proj_ln_kernel<<<ROWS/64, 256>>>(bo, gamma, beta, out);
}

// round 15
// speedup vs baseline: 1.4046x; 1.4009x over previous
#include <cuda_runtime.h>
#include <cuda_bf16.h>
#include <mma.h>
#include <math.h>
#include <stdint.h>
using namespace nvcuda;

#define BATCH 8
#define SEQ   2048
#define DIM   256
#define ROWS  (BATCH*SEQ)
#define LOG2E 1.4426950408889634f

__device__ __align__(16) float g_WT[4*DIM*DIM];
__device__ __align__(16) float g_loc[ROWS*DIM];
__device__ __align__(16) __nv_bfloat16 g_WTh[4*DIM*DIM], g_WTl[4*DIM*DIM];
__device__ __align__(16) __nv_bfloat16 g_Xh[ROWS*DIM], g_Xl[ROWS*DIM];
__device__ __align__(16) __nv_bfloat16 g_Qh[ROWS*DIM], g_Ql[ROWS*DIM];
__device__ __align__(16) __nv_bfloat16 g_Kh[ROWS*DIM], g_Kl[ROWS*DIM];
__device__ __align__(16) __nv_bfloat16 g_Vh[ROWS*DIM], g_Vl[ROWS*DIM];

__device__ __forceinline__ float fexp2(float x){ float y; asm("ex2.approx.ftz.f32 %0, %1;" : "=f"(y) : "f"(x)); return y; }
#define FMA4(o,a,b) do{ (o).x=fmaf((a),(b).x,(o).x); (o).y=fmaf((a),(b).y,(o).y); \
                        (o).z=fmaf((a),(b).z,(o).z); (o).w=fmaf((a),(b).w,(o).w);}while(0)

__device__ __forceinline__ uint32_t packbf(__nv_bfloat16 a, __nv_bfloat16 b){
    return (uint32_t)__bfloat16_as_ushort(a) | ((uint32_t)__bfloat16_as_ushort(b)<<16);
}
__device__ __forceinline__ void split4(float4 v, uint2& h, uint2& l){
    __nv_bfloat16 hx=__float2bfloat16(v.x), hy=__float2bfloat16(v.y), hz=__float2bfloat16(v.z), hw=__float2bfloat16(v.w);
    h.x = packbf(hx,hy); h.y = packbf(hz,hw);
    l.x = packbf(__float2bfloat16(v.x-__bfloat162float(hx)), __float2bfloat16(v.y-__bfloat162float(hy)));
    l.y = packbf(__float2bfloat16(v.z-__bfloat162float(hz)), __float2bfloat16(v.w-__bfloat162float(hw)));
}
__device__ __forceinline__ void cp16(void* s, const void* g){
    uint32_t a = (uint32_t)__cvta_generic_to_shared(s);
    asm volatile("cp.async.cg.shared.global [%0], [%1], 16;" :: "r"(a), "l"(g) : "memory");
}
#define CP_COMMIT() asm volatile("cp.async.commit_group;" ::: "memory")
#define CP_WAIT1()  asm volatile("cp.async.wait_group 1;" ::: "memory")

// ---- raw mma helpers ----
__device__ __forceinline__ void ldsm4(uint32_t* r, uint32_t addr){
    asm volatile("ldmatrix.sync.aligned.m8n8.x4.shared.b16 {%0,%1,%2,%3}, [%4];"
        : "=r"(r[0]),"=r"(r[1]),"=r"(r[2]),"=r"(r[3]) : "r"(addr));
}
__device__ __forceinline__ void ldsm4t(uint32_t* r, uint32_t addr){
    asm volatile("ldmatrix.sync.aligned.m8n8.x4.trans.shared.b16 {%0,%1,%2,%3}, [%4];"
        : "=r"(r[0]),"=r"(r[1]),"=r"(r[2]),"=r"(r[3]) : "r"(addr));
}
__device__ __forceinline__ void mma16816(float* c, const uint32_t* a, const uint32_t* b){
    asm volatile("mma.sync.aligned.m16n8k16.row.col.f32.bf16.bf16.f32 "
        "{%0,%1,%2,%3}, {%4,%5,%6,%7}, {%8,%9}, {%0,%1,%2,%3};"
        : "+f"(c[0]),"+f"(c[1]),"+f"(c[2]),"+f"(c[3])
        : "r"(a[0]),"r"(a[1]),"r"(a[2]),"r"(a[3]), "r"(b[0]),"r"(b[1]));
}

// ---------------- weight transpose + hi/lo split ----------------
__global__ void transpose_w_kernel(const float* __restrict__ Wq, const float* __restrict__ Wk,
                                   const float* __restrict__ Wv, const float* __restrict__ Wo){
    int m = blockIdx.x;
    const float* W = (m==0)?Wq:((m==1)?Wk:((m==2)?Wv:Wo));
    float* WT = g_WT + (size_t)m*DIM*DIM;
    __nv_bfloat16* WTh = g_WTh + (size_t)m*DIM*DIM;
    __nv_bfloat16* WTl = g_WTl + (size_t)m*DIM*DIM;
    for (int idx = threadIdx.x; idx < DIM*DIM; idx += blockDim.x){
        float w = W[(idx&255)*DIM + (idx>>8)];
        WT[idx] = w;
        __nv_bfloat16 h = __float2bfloat16(w);
        WTh[idx] = h;
        WTl[idx] = __float2bfloat16(w - __bfloat162float(h));
    }
}
__global__ void split_x_kernel(const float* __restrict__ x){
    int idx = blockIdx.x*blockDim.x + threadIdx.x;
    float4 v = *(const float4*)(x + (size_t)idx*4);
    uint2 h,l; split4(v,h,l);
    *(uint2*)(g_Xh + (size_t)idx*4) = h;
    *(uint2*)(g_Xl + (size_t)idx*4) = l;
}

// ---------------- QKV projections: bf16-split WMMA ----------------
#define XS 72
#define WS 264
#define QK_XH 0
#define QK_XL 9216
#define QK_W  18432
#define QK_WL (QK_W + 33792)
#define SMEM_QKV (QK_W + 67584)

__global__ void __launch_bounds__(256,2) qkv_wmma_kernel(
        const float* __restrict__ bq, const float* __restrict__ bk, const float* __restrict__ bv){
    extern __shared__ char smch[];
    __nv_bfloat16* Xh = (__nv_bfloat16*)(smch+QK_XH);
    __nv_bfloat16* Xl = (__nv_bfloat16*)(smch+QK_XL);
    __nv_bfloat16* Wh = (__nv_bfloat16*)(smch+QK_W);
    __nv_bfloat16* Wl = (__nv_bfloat16*)(smch+QK_WL);
    float* Of = (float*)(smch+QK_W);
    int tid = threadIdx.x, wid = tid>>5;
    int m = blockIdx.y, r0 = blockIdx.x*64;
    int mw = wid&3, np = wid>>2;
    const __nv_bfloat16* WTh = g_WTh + (size_t)m*DIM*DIM;
    const __nv_bfloat16* WTl = g_WTl + (size_t)m*DIM*DIM;

    wmma::fragment<wmma::accumulator,16,16,16,float> acc[8];
    #pragma unroll
    for (int j=0;j<8;j++) wmma::fill_fragment(acc[j], 0.f);

    for (int ck = 0; ck < 4; ++ck){
        __syncthreads();
        #pragma unroll
        for (int it=0; it<2; ++it){
            int idx = tid + it*256;
            int r = idx>>3, c8 = idx&7;
            size_t gsrc = (size_t)(r0+r)*DIM + ck*64 + c8*8;
            *(uint4*)(Xh + r*XS + c8*8) = *(const uint4*)(g_Xh + gsrc);
            *(uint4*)(Xl + r*XS + c8*8) = *(const uint4*)(g_Xl + gsrc);
        }
        #pragma unroll
        for (int it=0; it<8; ++it){
            int idx = tid + it*256;
            int dd = idx>>5, c8 = idx&31;
            size_t gsrc = (size_t)(ck*64+dd)*DIM + c8*8;
            *(uint4*)(Wh + dd*WS + c8*8) = *(const uint4*)(WTh + gsrc);
            *(uint4*)(Wl + dd*WS + c8*8) = *(const uint4*)(WTl + gsrc);
        }
        __syncthreads();
        #pragma unroll
        for (int k=0;k<4;++k){
            wmma::fragment<wmma::matrix_a,16,16,16,__nv_bfloat16,wmma::row_major> ah, al;
            wmma::load_matrix_sync(ah, Xh + mw*16*XS + k*16, XS);
            wmma::load_matrix_sync(al, Xl + mw*16*XS + k*16, XS);
            #pragma unroll
            for (int j=0;j<8;++j){
                int n0 = np*128 + j*16;
                wmma::fragment<wmma::matrix_b,16,16,16,__nv_bfloat16,wmma::row_major> bh, bl;
                wmma::load_matrix_sync(bh, Wh + k*16*WS + n0, WS);
                wmma::load_matrix_sync(bl, Wl + k*16*WS + n0, WS);
                wmma::mma_sync(acc[j], ah, bh, acc[j]);
                wmma::mma_sync(acc[j], al, bh, acc[j]);
                wmma::mma_sync(acc[j], ah, bl, acc[j]);
            }
        }
    }
    __syncthreads();
    #pragma unroll
    for (int j=0;j<8;++j)
        wmma::store_matrix_sync(Of + mw*16*WS + np*128 + j*16, acc[j], WS, wmma::mem_row_major);
    __syncthreads();

    const float* bias = (m==0)?bq:((m==1)?bk:bv);
    __nv_bfloat16* oh = (m==0)?g_Qh:((m==1)?g_Kh:g_Vh);
    __nv_bfloat16* ol = (m==0)?g_Ql:((m==1)?g_Kl:g_Vl);
    int row = tid>>2, part = tid&3;
    #pragma unroll
    for (int c4=0;c4<16;++c4){
        float4 v = *(const float4*)(Of + row*WS + part*64 + c4*4);
        float4 bb = *(const float4*)(bias + part*64 + c4*4);
        v.x+=bb.x; v.y+=bb.y; v.z+=bb.z; v.w+=bb.w;
        uint2 h,l; split4(v,h,l);
        size_t off = (size_t)(r0+row)*DIM + part*64 + c4*4;
        *(uint2*)(oh+off) = h; *(uint2*)(ol+off) = l;
    }
}

// ---------------- raw-mma flash attention: register softmax, no P smem ----------------
// q-tile 128 (8 warps x 16-row strips), k-tile 16 double-buffered. Grid = (16, 8) -> 1 wave.
#define AQH 0
#define AQL 67584
#define AKV 135168
#define KVB 8448                 // one 16x264 bf16 buffer
#define SMEM_ATTN (AKV + 8*KVB)  // 202752

__device__ __forceinline__ void stageKV(char* sm, size_t bb, int kt, int sel, int tid){
    size_t gsrc = bb + (size_t)kt*16*DIM;
    #pragma unroll
    for (int it=0; it<2; ++it){
        int idx = tid + it*256;
        int r = idx>>5, c8 = idx&31;
        int so = r*528 + c8*16;
        size_t go = gsrc + (size_t)r*DIM + c8*8;
        cp16(sm + AKV + sel*KVB + so,     g_Kh + go);
        cp16(sm + AKV + (2+sel)*KVB + so, g_Kl + go);
        cp16(sm + AKV + (4+sel)*KVB + so, g_Vh + go);
        cp16(sm + AKV + (6+sel)*KVB + so, g_Vl + go);
    }
}

__global__ void __launch_bounds__(256,1) attn_mma_kernel(){
    extern __shared__ char sm[];
    const uint32_t sbase = (uint32_t)__cvta_generic_to_shared(sm);
    int tid = threadIdx.x, wid = tid>>5, L = tid&31;
    int b = blockIdx.y, q0 = blockIdx.x*128;
    size_t bb = (size_t)b*SEQ*DIM;

    // prologue staging: kt=0 -> buf0, kt=1 -> buf1
    stageKV(sm, bb, 0, 0, tid); CP_COMMIT();
    stageKV(sm, bb, 1, 1, tid); CP_COMMIT();

    // stage Q (plain loads, once)
    #pragma unroll
    for (int it=0; it<16; ++it){
        int idx = tid + it*256;
        int r = idx>>5, c8 = idx&31;
        size_t go = bb + (size_t)(q0+r)*DIM + c8*8;
        *(uint4*)(sm + AQH + r*528 + c8*16) = *(const uint4*)(g_Qh + go);
        *(uint4*)(sm + AQL + r*528 + c8*16) = *(const uint4*)(g_Ql + go);
    }

    // per-lane ldmatrix base addresses
    uint32_t qhB = sbase + AQH + (uint32_t)((wid*16 + (L&15))*528 + (L>>4)*16);
    uint32_t qlB = qhB + (AQL - AQH);
    uint32_t kOff = (uint32_t)(((L&7) + ((L>>4)<<3))*528 + ((L>>3)&1)*16);
    uint32_t vOff = (uint32_t)((L&15)*528 + (L>>4)*16);

    float o[32][4];
    #pragma unroll
    for (int j=0;j<32;++j){ o[j][0]=0.f; o[j][1]=0.f; o[j][2]=0.f; o[j][3]=0.f; }
    float ps0 = 0.f, ps1 = 0.f;

    CP_WAIT1();
    __syncthreads();

    for (int kt = 0; kt < SEQ/16; ++kt){
        int sel = kt&1;
        uint32_t kB  = sbase + AKV + sel*KVB + kOff;
        uint32_t kBl = kB + 2*KVB;
        uint32_t vB  = sbase + AKV + (4+sel)*KVB + vOff;
        uint32_t vBl = vB + 2*KVB;

        // ---- S = (Qh+Ql)(Kh+Kl)^T, 3 term-chains x 2 n8-blocks ----
        float shh[2][4]={{0,0,0,0},{0,0,0,0}};
        float slh[2][4]={{0,0,0,0},{0,0,0,0}};
        float shl[2][4]={{0,0,0,0},{0,0,0,0}};
        #pragma unroll
        for (int kd=0; kd<16; ++kd){
            uint32_t ah[4], al[4], bh[4], bl[4];
            ldsm4(ah, qhB + kd*32);
            ldsm4(al, qlB + kd*32);
            ldsm4(bh, kB  + kd*32);
            ldsm4(bl, kBl + kd*32);
            mma16816(shh[0], ah, bh+0); mma16816(shh[1], ah, bh+2);
            mma16816(slh[0], al, bh+0); mma16816(slh[1], al, bh+2);
            mma16816(shl[0], ah, bl+0); mma16816(shl[1], ah, bl+2);
        }

        // ---- softmax in registers: S-acc IS the PV A-operand layout ----
        float p[8];
        #pragma unroll
        for (int blk=0; blk<2; ++blk)
            #pragma unroll
            for (int e=0; e<4; ++e){
                float s = shh[blk][e] + slh[blk][e] + shl[blk][e];
                p[blk*4+e] = fexp2(s*LOG2E);
            }
        ps0 += (p[0]+p[1]) + (p[4]+p[5]);
        ps1 += (p[2]+p[3]) + (p[6]+p[7]);
        uint32_t ah4[4], al4[4];
        #pragma unroll
        for (int q=0; q<4; ++q){
            float pa = p[2*q], pb = p[2*q+1];
            __nv_bfloat16 ha = __float2bfloat16(pa), hb = __float2bfloat16(pb);
            ah4[q] = packbf(ha, hb);
            al4[q] = packbf(__float2bfloat16(pa-__bfloat162float(ha)),
                            __float2bfloat16(pb-__bfloat162float(hb)));
        }

        // ---- PV: O += (Ph+Pl)(Vh+Vl), A from registers, B via ldmatrix.trans ----
        #pragma unroll
        for (int j=0; j<16; ++j){
            uint32_t bh[4], bl[4];
            ldsm4t(bh, vB  + j*32);
            ldsm4t(bl, vBl + j*32);
            mma16816(o[2*j],   ah4, bh+0); mma16816(o[2*j+1], ah4, bh+2);
            mma16816(o[2*j],   al4, bh+0); mma16816(o[2*j+1], al4, bh+2);
            mma16816(o[2*j],   ah4, bl+0); mma16816(o[2*j+1], ah4, bl+2);
        }

        __syncthreads();                                  // all reads of buf[sel] done
        if (kt+2 < SEQ/16) stageKV(sm, bb, kt+2, sel, tid);
        CP_COMMIT();
        CP_WAIT1();                                       // buf[(kt+1)&1] ready
        __syncthreads();
    }

    // ---- epilogue: finish row sums in-warp, scale, write ----
    ps0 += __shfl_xor_sync(0xffffffffu, ps0, 1);
    ps0 += __shfl_xor_sync(0xffffffffu, ps0, 2);
    ps1 += __shfl_xor_sync(0xffffffffu, ps1, 1);
    ps1 += __shfl_xor_sync(0xffffffffu, ps1, 2);
    float inv0 = 1.0f/ps0, inv1 = 1.0f/ps1;
    int g = L>>2, t = L&3;
    float* r0p = g_loc + (size_t)(b*SEQ + q0 + wid*16 + g)*DIM;
    float* r1p = r0p + (size_t)8*DIM;
    #pragma unroll
    for (int j=0; j<32; ++j){
        int col = j*8 + 2*t;
        float2 v0 = make_float2(o[j][0]*inv0, o[j][1]*inv0);
        float2 v1 = make_float2(o[j][2]*inv1, o[j][3]*inv1);
        *(float2*)(r0p + col) = v0;
        *(float2*)(r1p + col) = v1;
    }
}

// ---------------- fp32 64x256 GEMM mainloop (proj) ----------------
__device__ __forceinline__ void gemm64x256(const float* __restrict__ A, int r0, const float* __restrict__ WT,
                                           float* Xs, float* WsT, int tx, int ty, int tid, float4 acc[4][4]){
    for (int dc = 0; dc < 8; ++dc){
        #pragma unroll
        for (int it = 0; it < 2; ++it){
            int idx = tid + it*256; int r = idx>>3, d4 = idx&7;
            float4 v = *(const float4*)(A + (size_t)(r0+r)*DIM + dc*32 + d4*4);
            float* p = &Xs[r*33 + d4*4]; p[0]=v.x; p[1]=v.y; p[2]=v.z; p[3]=v.w;
        }
        #pragma unroll
        for (int it = 0; it < 8; ++it){
            int idx = tid + it*256; int dd = idx>>6, c4 = idx&63;
            *(float4*)&WsT[dd*256 + c4*4] = *(const float4*)(WT + (size_t)(dc*32+dd)*DIM + c4*4);
        }
        __syncthreads();
        #pragma unroll 8
        for (int dd = 0; dd < 32; ++dd){
            float a[4];
            #pragma unroll
            for (int i = 0; i < 4; ++i) a[i] = Xs[(4*ty+i)*33 + dd];
            #pragma unroll
            for (int j = 0; j < 4; ++j){
                float4 b = *(float4*)&WsT[dd*256 + 4*tx + 64*j];
                #pragma unroll
                for (int i = 0; i < 4; ++i) FMA4(acc[i][j], a[i], b);
            }
        }
        __syncthreads();
    }
}

// ---------------- output projection + LayerNorm + LeakyReLU ----------------
__global__ __launch_bounds__(256) void proj_ln_kernel(const float* __restrict__ bo,
        const float* __restrict__ gamma, const float* __restrict__ beta, float* __restrict__ out){
    __shared__ float Xs[64*33];
    __shared__ float WsT[32*256];
    const float* WT = g_WT + (size_t)3*DIM*DIM;
    int r0 = blockIdx.x*64;
    int tid = threadIdx.x, tx = tid&15, ty = tid>>4;
    float4 acc[4][4];
    #pragma unroll
    for (int i=0;i<4;i++){ acc[i][0]=acc[i][1]=acc[i][2]=acc[i][3]=make_float4(0.f,0.f,0.f,0.f); }
    gemm64x256(g_loc, r0, WT, Xs, WsT, tx, ty, tid, acc);
    #pragma unroll
    for (int j=0;j<4;j++){
        float4 bbv = *(const float4*)(bo + 4*tx + 64*j);
        #pragma unroll
        for (int i=0;i<4;i++){ acc[i][j].x+=bbv.x; acc[i][j].y+=bbv.y; acc[i][j].z+=bbv.z; acc[i][j].w+=bbv.w; }
    }
    #pragma unroll
    for (int i=0;i<4;i++){
        float ssum = 0.f;
        #pragma unroll
        for (int j=0;j<4;j++) ssum += acc[i][j].x + acc[i][j].y + acc[i][j].z + acc[i][j].w;
        #pragma unroll
        for (int off=8; off>=1; off>>=1) ssum += __shfl_xor_sync(0xffffffffu, ssum, off);
        float mu = ssum * (1.0f/DIM);
        float vsum = 0.f;
        #pragma unroll
        for (int j=0;j<4;j++){
            float dx=acc[i][j].x-mu, dy=acc[i][j].y-mu, dz=acc[i][j].z-mu, dw=acc[i][j].w-mu;
            vsum += dx*dx + dy*dy + dz*dz + dw*dw;
        }
        #pragma unroll
        for (int off=8; off>=1; off>>=1) vsum += __shfl_xor_sync(0xffffffffu, vsum, off);
        float rstd = rsqrtf(vsum*(1.0f/DIM) + 1e-5f);
        #pragma unroll
        for (int j=0;j<4;j++){
            float4 g  = *(const float4*)(gamma + 4*tx + 64*j);
            float4 bt = *(const float4*)(beta  + 4*tx + 64*j);
            float4 h  = acc[i][j]; float4 y;
            y.x=(h.x-mu)*rstd*g.x+bt.x; y.x=(y.x>=0.f)?y.x:0.01f*y.x;
            y.y=(h.y-mu)*rstd*g.y+bt.y; y.y=(y.y>=0.f)?y.y:0.01f*y.y;
            y.z=(h.z-mu)*rstd*g.z+bt.z; y.z=(y.z>=0.f)?y.z:0.01f*y.z;
            y.w=(h.w-mu)*rstd*g.w+bt.w; y.w=(y.w>=0.f)?y.w:0.01f*y.w;
            *(float4*)(out + (size_t)(r0+4*ty+i)*DIM + 4*tx + 64*j) = y;
        }
    }
}

// ---------------- entry ----------------
extern "C" void kernel_launch(void* const* d_in, const int* in_sizes, int n_in,
                              void* d_out, int out_size){
    const float* x     = (const float*)d_in[0];
    const float* bq    = (const float*)d_in[2];
    const float* bk    = (const float*)d_in[4];
    const float* bv    = (const float*)d_in[6];
    const float* bo    = (const float*)d_in[8];
    const float* gamma = (const float*)d_in[9];
    const float* beta  = (const float*)d_in[10];
    float* out = (float*)d_out;

    cudaFuncSetAttribute(qkv_wmma_kernel, cudaFuncAttributeMaxDynamicSharedMemorySize, SMEM_QKV);
    cudaFuncSetAttribute(attn_mma_kernel, cudaFuncAttributeMaxDynamicSharedMemorySize, SMEM_ATTN);

    transpose_w_kernel<<<4, 256>>>((const float*)d_in[1], (const float*)d_in[3],
                                   (const float*)d_in[5], (const float*)d_in[7]);
    split_x_kernel<<<ROWS*DIM/4/256, 256>>>(x);
    qkv_wmma_kernel<<<dim3(ROWS/64, 3), 256, SMEM_QKV>>>(bq, bk, bv);
    attn_mma_kernel<<<dim3(SEQ/128, BATCH), 256, SMEM_ATTN>>>();
    proj_ln_kernel<<<ROWS/64, 256>>>(bo, gamma, beta, out);
}

// round 16
// speedup vs baseline: 1.5612x; 1.1115x over previous
#include <cuda_runtime.h>
#include <cuda_bf16.h>
#include <mma.h>
#include <math.h>
#include <stdint.h>
using namespace nvcuda;

#define BATCH 8
#define SEQ   2048
#define DIM   256
#define ROWS  (BATCH*SEQ)
#define LOG2E 1.4426950408889634f

__device__ __align__(16) __nv_bfloat16 g_WTh[4*DIM*DIM], g_WTl[4*DIM*DIM];
__device__ __align__(16) __nv_bfloat16 g_Xh[ROWS*DIM], g_Xl[ROWS*DIM];
__device__ __align__(16) __nv_bfloat16 g_Qh[ROWS*DIM], g_Ql[ROWS*DIM];
__device__ __align__(16) __nv_bfloat16 g_Kh[ROWS*DIM], g_Kl[ROWS*DIM];
__device__ __align__(16) __nv_bfloat16 g_Vh[ROWS*DIM], g_Vl[ROWS*DIM];
__device__ __align__(16) __nv_bfloat16 g_LOCh[ROWS*DIM], g_LOCl[ROWS*DIM];

__device__ __forceinline__ float fexp2(float x){ float y; asm("ex2.approx.ftz.f32 %0, %1;" : "=f"(y) : "f"(x)); return y; }

__device__ __forceinline__ uint32_t packbf(__nv_bfloat16 a, __nv_bfloat16 b){
    return (uint32_t)__bfloat16_as_ushort(a) | ((uint32_t)__bfloat16_as_ushort(b)<<16);
}
__device__ __forceinline__ void split4(float4 v, uint2& h, uint2& l){
    __nv_bfloat16 hx=__float2bfloat16(v.x), hy=__float2bfloat16(v.y), hz=__float2bfloat16(v.z), hw=__float2bfloat16(v.w);
    h.x = packbf(hx,hy); h.y = packbf(hz,hw);
    l.x = packbf(__float2bfloat16(v.x-__bfloat162float(hx)), __float2bfloat16(v.y-__bfloat162float(hy)));
    l.y = packbf(__float2bfloat16(v.z-__bfloat162float(hz)), __float2bfloat16(v.w-__bfloat162float(hw)));
}
__device__ __forceinline__ void cp16(void* s, const void* g){
    uint32_t a = (uint32_t)__cvta_generic_to_shared(s);
    asm volatile("cp.async.cg.shared.global [%0], [%1], 16;" :: "r"(a), "l"(g) : "memory");
}
#define CP_COMMIT() asm volatile("cp.async.commit_group;" ::: "memory")
#define CP_WAIT1()  asm volatile("cp.async.wait_group 1;" ::: "memory")

__device__ __forceinline__ void ldsm4(uint32_t* r, uint32_t addr){
    asm volatile("ldmatrix.sync.aligned.m8n8.x4.shared.b16 {%0,%1,%2,%3}, [%4];"
        : "=r"(r[0]),"=r"(r[1]),"=r"(r[2]),"=r"(r[3]) : "r"(addr));
}
__device__ __forceinline__ void ldsm4t(uint32_t* r, uint32_t addr){
    asm volatile("ldmatrix.sync.aligned.m8n8.x4.trans.shared.b16 {%0,%1,%2,%3}, [%4];"
        : "=r"(r[0]),"=r"(r[1]),"=r"(r[2]),"=r"(r[3]) : "r"(addr));
}
__device__ __forceinline__ void mma16816(float* c, const uint32_t* a, const uint32_t* b){
    asm volatile("mma.sync.aligned.m16n8k16.row.col.f32.bf16.bf16.f32 "
        "{%0,%1,%2,%3}, {%4,%5,%6,%7}, {%8,%9}, {%0,%1,%2,%3};"
        : "+f"(c[0]),"+f"(c[1]),"+f"(c[2]),"+f"(c[3])
        : "r"(a[0]),"r"(a[1]),"r"(a[2]),"r"(a[3]), "r"(b[0]),"r"(b[1]));
}

// ---------------- weight transpose + hi/lo split ----------------
__global__ void transpose_w_kernel(const float* __restrict__ Wq, const float* __restrict__ Wk,
                                   const float* __restrict__ Wv, const float* __restrict__ Wo){
    int m = blockIdx.x;
    const float* W = (m==0)?Wq:((m==1)?Wk:((m==2)?Wv:Wo));
    __nv_bfloat16* WTh = g_WTh + (size_t)m*DIM*DIM;
    __nv_bfloat16* WTl = g_WTl + (size_t)m*DIM*DIM;
    for (int idx = threadIdx.x; idx < DIM*DIM; idx += blockDim.x){
        float w = W[(idx&255)*DIM + (idx>>8)];
        __nv_bfloat16 h = __float2bfloat16(w);
        WTh[idx] = h;
        WTl[idx] = __float2bfloat16(w - __bfloat162float(h));
    }
}
__global__ void split_x_kernel(const float* __restrict__ x){
    int idx = blockIdx.x*blockDim.x + threadIdx.x;
    float4 v = *(const float4*)(x + (size_t)idx*4);
    uint2 h,l; split4(v,h,l);
    *(uint2*)(g_Xh + (size_t)idx*4) = h;
    *(uint2*)(g_Xl + (size_t)idx*4) = l;
}

// ---------------- shared WMMA 64x256 bf16-split GEMM mainloop ----------------
#define XS 72
#define WS 264
#define QK_XH 0
#define QK_XL 9216
#define QK_W  18432
#define QK_WL (QK_W + 33792)
#define SMEM_QKV (QK_W + 67584)

__device__ __forceinline__ void gemm_wmma_64x256(
        char* smch, const __nv_bfloat16* __restrict__ Ah, const __nv_bfloat16* __restrict__ Al,
        const __nv_bfloat16* __restrict__ WTh, const __nv_bfloat16* __restrict__ WTl,
        int r0, int tid, int mw, int np,
        wmma::fragment<wmma::accumulator,16,16,16,float>* acc){
    __nv_bfloat16* Xh = (__nv_bfloat16*)(smch+QK_XH);
    __nv_bfloat16* Xl = (__nv_bfloat16*)(smch+QK_XL);
    __nv_bfloat16* Wh = (__nv_bfloat16*)(smch+QK_W);
    __nv_bfloat16* Wl = (__nv_bfloat16*)(smch+QK_WL);
    for (int ck = 0; ck < 4; ++ck){
        __syncthreads();
        #pragma unroll
        for (int it=0; it<2; ++it){
            int idx = tid + it*256;
            int r = idx>>3, c8 = idx&7;
            size_t gsrc = (size_t)(r0+r)*DIM + ck*64 + c8*8;
            *(uint4*)(Xh + r*XS + c8*8) = *(const uint4*)(Ah + gsrc);
            *(uint4*)(Xl + r*XS + c8*8) = *(const uint4*)(Al + gsrc);
        }
        #pragma unroll
        for (int it=0; it<8; ++it){
            int idx = tid + it*256;
            int dd = idx>>5, c8 = idx&31;
            size_t gsrc = (size_t)(ck*64+dd)*DIM + c8*8;
            *(uint4*)(Wh + dd*WS + c8*8) = *(const uint4*)(WTh + gsrc);
            *(uint4*)(Wl + dd*WS + c8*8) = *(const uint4*)(WTl + gsrc);
        }
        __syncthreads();
        #pragma unroll
        for (int k=0;k<4;++k){
            wmma::fragment<wmma::matrix_a,16,16,16,__nv_bfloat16,wmma::row_major> ah, al;
            wmma::load_matrix_sync(ah, Xh + mw*16*XS + k*16, XS);
            wmma::load_matrix_sync(al, Xl + mw*16*XS + k*16, XS);
            #pragma unroll
            for (int j=0;j<8;++j){
                int n0 = np*128 + j*16;
                wmma::fragment<wmma::matrix_b,16,16,16,__nv_bfloat16,wmma::row_major> bh, bl;
                wmma::load_matrix_sync(bh, Wh + k*16*WS + n0, WS);
                wmma::load_matrix_sync(bl, Wl + k*16*WS + n0, WS);
                wmma::mma_sync(acc[j], ah, bh, acc[j]);
                wmma::mma_sync(acc[j], al, bh, acc[j]);
                wmma::mma_sync(acc[j], ah, bl, acc[j]);
            }
        }
    }
}

// ---------------- QKV projections ----------------
__global__ void __launch_bounds__(256,2) qkv_wmma_kernel(
        const float* __restrict__ bq, const float* __restrict__ bk, const float* __restrict__ bv){
    extern __shared__ char smch[];
    float* Of = (float*)(smch+QK_W);
    int tid = threadIdx.x, wid = tid>>5;
    int m = blockIdx.y, r0 = blockIdx.x*64;
    int mw = wid&3, np = wid>>2;

    wmma::fragment<wmma::accumulator,16,16,16,float> acc[8];
    #pragma unroll
    for (int j=0;j<8;j++) wmma::fill_fragment(acc[j], 0.f);

    gemm_wmma_64x256(smch, g_Xh, g_Xl,
                     g_WTh + (size_t)m*DIM*DIM, g_WTl + (size_t)m*DIM*DIM,
                     r0, tid, mw, np, acc);
    __syncthreads();
    #pragma unroll
    for (int j=0;j<8;++j)
        wmma::store_matrix_sync(Of + mw*16*WS + np*128 + j*16, acc[j], WS, wmma::mem_row_major);
    __syncthreads();

    const float* bias = (m==0)?bq:((m==1)?bk:bv);
    __nv_bfloat16* oh = (m==0)?g_Qh:((m==1)?g_Kh:g_Vh);
    __nv_bfloat16* ol = (m==0)?g_Ql:((m==1)?g_Kl:g_Vl);
    int row = tid>>2, part = tid&3;
    #pragma unroll
    for (int c4=0;c4<16;++c4){
        float4 v = *(const float4*)(Of + row*WS + part*64 + c4*4);
        float4 bb = *(const float4*)(bias + part*64 + c4*4);
        v.x+=bb.x; v.y+=bb.y; v.z+=bb.z; v.w+=bb.w;
        uint2 h,l; split4(v,h,l);
        size_t off = (size_t)(r0+row)*DIM + part*64 + c4*4;
        *(uint2*)(oh+off) = h; *(uint2*)(ol+off) = l;
    }
}

// ---------------- raw-mma flash attention: 32-key macro-iters, Q amortized ----------------
#define AQH 0
#define AQL 67584
#define AKV 135168
#define KVB 8448                 // one 16x264 bf16 buffer
#define SMEM_ATTN (AKV + 8*KVB)  // 202752

__device__ __forceinline__ void stageK(char* sm, size_t bb, int kt, int sel, int tid){
    size_t gsrc = bb + (size_t)kt*16*DIM;
    #pragma unroll
    for (int it=0; it<2; ++it){
        int idx = tid + it*256;
        int r = idx>>5, c8 = idx&31;
        int so = r*528 + c8*16;
        size_t go = gsrc + (size_t)r*DIM + c8*8;
        cp16(sm + AKV + sel*KVB + so,     g_Kh + go);
        cp16(sm + AKV + (2+sel)*KVB + so, g_Kl + go);
    }
}
__device__ __forceinline__ void stageV(char* sm, size_t bb, int kt, int sel, int tid){
    size_t gsrc = bb + (size_t)kt*16*DIM;
    #pragma unroll
    for (int it=0; it<2; ++it){
        int idx = tid + it*256;
        int r = idx>>5, c8 = idx&31;
        int so = r*528 + c8*16;
        size_t go = gsrc + (size_t)r*DIM + c8*8;
        cp16(sm + AKV + (4+sel)*KVB + so, g_Vh + go);
        cp16(sm + AKV + (6+sel)*KVB + so, g_Vl + go);
    }
}

__global__ void __launch_bounds__(256,1) attn_mma_kernel(){
    extern __shared__ char sm[];
    const uint32_t sbase = (uint32_t)__cvta_generic_to_shared(sm);
    int tid = threadIdx.x, wid = tid>>5, L = tid&31;
    int b = blockIdx.y, q0 = blockIdx.x*128;
    size_t bb = (size_t)b*SEQ*DIM;

    // prologue: K(0),K(1) as group0 ; V(0),V(1) as group1
    stageK(sm, bb, 0, 0, tid); stageK(sm, bb, 1, 1, tid); CP_COMMIT();
    stageV(sm, bb, 0, 0, tid); stageV(sm, bb, 1, 1, tid); CP_COMMIT();

    // stage Q once (plain loads)
    #pragma unroll
    for (int it=0; it<16; ++it){
        int idx = tid + it*256;
        int r = idx>>5, c8 = idx&31;
        size_t go = bb + (size_t)(q0+r)*DIM + c8*8;
        *(uint4*)(sm + AQH + r*528 + c8*16) = *(const uint4*)(g_Qh + go);
        *(uint4*)(sm + AQL + r*528 + c8*16) = *(const uint4*)(g_Ql + go);
    }

    uint32_t qhB = sbase + AQH + (uint32_t)((wid*16 + (L&15))*528 + (L>>4)*16);
    uint32_t qlB = qhB + (AQL - AQH);
    uint32_t kOff = (uint32_t)(((L&7) + ((L>>4)<<3))*528 + ((L>>3)&1)*16);
    uint32_t vOff = (uint32_t)((L&15)*528 + (L>>4)*16);
    const uint32_t kB0  = sbase + AKV + kOff,       kB0l = kB0 + 2*KVB;
    const uint32_t kB1  = kB0 + KVB,                kB1l = kB0 + 3*KVB;
    const uint32_t vB0  = sbase + AKV + 4*KVB + vOff, vB0l = vB0 + 2*KVB;
    const uint32_t vB1  = vB0 + KVB,                vB1l = vB0 + 3*KVB;

    float o[32][4];
    #pragma unroll
    for (int j=0;j<32;++j){ o[j][0]=0.f; o[j][1]=0.f; o[j][2]=0.f; o[j][3]=0.f; }
    float ps0 = 0.f, ps1 = 0.f;

    CP_WAIT1();            // K(0),K(1) arrived
    __syncthreads();

    const int NMI = SEQ/32;    // 64 macro-iters of 32 keys
    for (int mi = 0; mi < NMI; ++mi){
        // ---- S over 32 keys: blocks 0,1 from buf0; 2,3 from buf1 ----
        float sA[4][4], sB[4][4];
        #pragma unroll
        for (int q=0;q<4;++q){
            sA[q][0]=sA[q][1]=sA[q][2]=sA[q][3]=0.f;
            sB[q][0]=sB[q][1]=sB[q][2]=sB[q][3]=0.f;
        }
        #pragma unroll
        for (int kd=0; kd<16; ++kd){
            uint32_t ah[4], al[4], b0h[4], b0l[4], b1h[4], b1l[4];
            ldsm4(ah, qhB + kd*32);
            ldsm4(al, qlB + kd*32);
            ldsm4(b0h, kB0  + kd*32);
            ldsm4(b0l, kB0l + kd*32);
            ldsm4(b1h, kB1  + kd*32);
            ldsm4(b1l, kB1l + kd*32);
            mma16816(sA[0], ah, b0h+0); mma16816(sA[1], ah, b0h+2);
            mma16816(sA[2], ah, b1h+0); mma16816(sA[3], ah, b1h+2);
            mma16816(sB[0], al, b0h+0); mma16816(sB[1], al, b0h+2);
            mma16816(sB[2], al, b1h+0); mma16816(sB[3], al, b1h+2);
            mma16816(sA[0], ah, b0l+0); mma16816(sA[1], ah, b0l+2);
            mma16816(sA[2], ah, b1l+0); mma16816(sA[3], ah, b1l+2);
        }

        // ---- softmax in registers: S-acc layout == PV A-operand layout ----
        float p[16];
        #pragma unroll
        for (int blk=0; blk<4; ++blk)
            #pragma unroll
            for (int e=0; e<4; ++e)
                p[blk*4+e] = fexp2((sA[blk][e] + sB[blk][e])*LOG2E);
        #pragma unroll
        for (int blk=0; blk<4; ++blk){
            ps0 += p[blk*4+0] + p[blk*4+1];
            ps1 += p[blk*4+2] + p[blk*4+3];
        }
        uint32_t a0h[4], a0l[4], a1h[4], a1l[4];
        #pragma unroll
        for (int q=0; q<4; ++q){
            float pa = p[2*q], pb = p[2*q+1];
            __nv_bfloat16 ha = __float2bfloat16(pa), hb = __float2bfloat16(pb);
            a0h[q] = packbf(ha, hb);
            a0l[q] = packbf(__float2bfloat16(pa-__bfloat162float(ha)),
                            __float2bfloat16(pb-__bfloat162float(hb)));
            float pc = p[8+2*q], pd = p[9+2*q];
            __nv_bfloat16 hc = __float2bfloat16(pc), hd = __float2bfloat16(pd);
            a1h[q] = packbf(hc, hd);
            a1l[q] = packbf(__float2bfloat16(pc-__bfloat162float(hc)),
                            __float2bfloat16(pd-__bfloat162float(hd)));
        }

        __syncthreads();                            // all K reads done
        int t2 = mi*2 + 2;
        if (t2 < SEQ/16){ stageK(sm, bb, t2, 0, tid); stageK(sm, bb, t2+1, 1, tid); }
        CP_COMMIT();                                // group K(next)
        CP_WAIT1();                                 // V(cur) done
        __syncthreads();

        // ---- PV: O += (P0h+P0l)(V0h+V0l) + (P1h+P1l)(V1h+V1l) ----
        #pragma unroll
        for (int j=0; j<16; ++j){
            uint32_t b0h[4], b0l[4], b1h[4], b1l[4];
            ldsm4t(b0h, vB0  + j*32);
            ldsm4t(b0l, vB0l + j*32);
            ldsm4t(b1h, vB1  + j*32);
            ldsm4t(b1l, vB1l + j*32);
            mma16816(o[2*j],   a0h, b0h+0); mma16816(o[2*j+1], a0h, b0h+2);
            mma16816(o[2*j],   a0l, b0h+0); mma16816(o[2*j+1], a0l, b0h+2);
            mma16816(o[2*j],   a0h, b0l+0); mma16816(o[2*j+1], a0h, b0l+2);
            mma16816(o[2*j],   a1h, b1h+0); mma16816(o[2*j+1], a1h, b1h+2);
            mma16816(o[2*j],   a1l, b1h+0); mma16816(o[2*j+1], a1l, b1h+2);
            mma16816(o[2*j],   a1h, b1l+0); mma16816(o[2*j+1], a1h, b1l+2);
        }

        __syncthreads();                            // all V reads done
        if (t2 < SEQ/16){ stageV(sm, bb, t2, 0, tid); stageV(sm, bb, t2+1, 1, tid); }
        CP_COMMIT();                                // group V(next)
        CP_WAIT1();                                 // K(next) done
        __syncthreads();
    }

    // ---- epilogue: reduce row sums in-warp, scale, write bf16-split loc ----
    ps0 += __shfl_xor_sync(0xffffffffu, ps0, 1);
    ps0 += __shfl_xor_sync(0xffffffffu, ps0, 2);
    ps1 += __shfl_xor_sync(0xffffffffu, ps1, 1);
    ps1 += __shfl_xor_sync(0xffffffffu, ps1, 2);
    float inv0 = 1.0f/ps0, inv1 = 1.0f/ps1;
    int g = L>>2, t = L&3;
    size_t r0o = (size_t)(b*SEQ + q0 + wid*16 + g)*DIM;
    size_t r1o = r0o + (size_t)8*DIM;
    #pragma unroll
    for (int j=0; j<32; ++j){
        int col = j*8 + 2*t;
        float v0 = o[j][0]*inv0, v1 = o[j][1]*inv0;
        float v2 = o[j][2]*inv1, v3 = o[j][3]*inv1;
        __nv_bfloat16 h0=__float2bfloat16(v0), h1=__float2bfloat16(v1);
        __nv_bfloat16 h2=__float2bfloat16(v2), h3=__float2bfloat16(v3);
        *(uint32_t*)(g_LOCh + r0o + col) = packbf(h0,h1);
        *(uint32_t*)(g_LOCl + r0o + col) = packbf(__float2bfloat16(v0-__bfloat162float(h0)),
                                                  __float2bfloat16(v1-__bfloat162float(h1)));
        *(uint32_t*)(g_LOCh + r1o + col) = packbf(h2,h3);
        *(uint32_t*)(g_LOCl + r1o + col) = packbf(__float2bfloat16(v2-__bfloat162float(h2)),
                                                  __float2bfloat16(v3-__bfloat162float(h3)));
    }
}

// ---------------- output projection (WMMA) + LayerNorm + LeakyReLU ----------------
__global__ void __launch_bounds__(256,2) proj_wmma_kernel(
        const float* __restrict__ bo, const float* __restrict__ gamma,
        const float* __restrict__ beta, float* __restrict__ out){
    extern __shared__ char smch[];
    float* Of = (float*)(smch+QK_W);
    int tid = threadIdx.x, wid = tid>>5;
    int r0 = blockIdx.x*64;
    int mw = wid&3, np = wid>>2;

    wmma::fragment<wmma::accumulator,16,16,16,float> acc[8];
    #pragma unroll
    for (int j=0;j<8;j++) wmma::fill_fragment(acc[j], 0.f);

    gemm_wmma_64x256(smch, g_LOCh, g_LOCl,
                     g_WTh + (size_t)3*DIM*DIM, g_WTl + (size_t)3*DIM*DIM,
                     r0, tid, mw, np, acc);
    __syncthreads();
    #pragma unroll
    for (int j=0;j<8;++j)
        wmma::store_matrix_sync(Of + mw*16*WS + np*128 + j*16, acc[j], WS, wmma::mem_row_major);
    __syncthreads();

    int row = tid>>2, part = tid&3;
    float* myrow = Of + row*WS + part*64;

    // add bias in place (each thread owns its slice; no cross-thread hazard)
    #pragma unroll
    for (int c4=0;c4<16;++c4){
        float4 v = *(const float4*)(myrow + c4*4);
        float4 bb = *(const float4*)(bo + part*64 + c4*4);
        v.x+=bb.x; v.y+=bb.y; v.z+=bb.z; v.w+=bb.w;
        *(float4*)(myrow + c4*4) = v;
    }

    // mean
    float ssum = 0.f;
    #pragma unroll
    for (int c4=0;c4<16;++c4){
        float4 v = *(const float4*)(myrow + c4*4);
        ssum += (v.x+v.y)+(v.z+v.w);
    }
    ssum += __shfl_xor_sync(0xffffffffu, ssum, 1);
    ssum += __shfl_xor_sync(0xffffffffu, ssum, 2);
    float mu = ssum * (1.0f/DIM);

    // variance
    float vsum = 0.f;
    #pragma unroll
    for (int c4=0;c4<16;++c4){
        float4 v = *(const float4*)(myrow + c4*4);
        float dx=v.x-mu, dy=v.y-mu, dz=v.z-mu, dw=v.w-mu;
        vsum += (dx*dx+dy*dy)+(dz*dz+dw*dw);
    }
    vsum += __shfl_xor_sync(0xffffffffu, vsum, 1);
    vsum += __shfl_xor_sync(0xffffffffu, vsum, 2);
    float rstd = rsqrtf(vsum*(1.0f/DIM) + 1e-5f);

    // normalize + affine + LeakyReLU + store
    float* gout = out + (size_t)(r0+row)*DIM + part*64;
    #pragma unroll
    for (int c4=0;c4<16;++c4){
        float4 h = *(const float4*)(myrow + c4*4);
        float4 g4 = *(const float4*)(gamma + part*64 + c4*4);
        float4 bt = *(const float4*)(beta  + part*64 + c4*4);
        float4 y;
        y.x=(h.x-mu)*rstd*g4.x+bt.x; y.x=(y.x>=0.f)?y.x:0.01f*y.x;
        y.y=(h.y-mu)*rstd*g4.y+bt.y; y.y=(y.y>=0.f)?y.y:0.01f*y.y;
        y.z=(h.z-mu)*rstd*g4.z+bt.z; y.z=(y.z>=0.f)?y.z:0.01f*y.z;
        y.w=(h.w-mu)*rstd*g4.w+bt.w; y.w=(y.w>=0.f)?y.w:0.01f*y.w;
        *(float4*)(gout + c4*4) = y;
    }
}

// ---------------- entry ----------------
extern "C" void kernel_launch(void* const* d_in, const int* in_sizes, int n_in,
                              void* d_out, int out_size){
    const float* x     = (const float*)d_in[0];
    const float* bq    = (const float*)d_in[2];
    const float* bk    = (const float*)d_in[4];
    const float* bv    = (const float*)d_in[6];
    const float* bo    = (const float*)d_in[8];
    const float* gamma = (const float*)d_in[9];
    const float* beta  = (const float*)d_in[10];
    float* out = (float*)d_out;

    cudaFuncSetAttribute(qkv_wmma_kernel,  cudaFuncAttributeMaxDynamicSharedMemorySize, SMEM_QKV);
    cudaFuncSetAttribute(proj_wmma_kernel, cudaFuncAttributeMaxDynamicSharedMemorySize, SMEM_QKV);
    cudaFuncSetAttribute(attn_mma_kernel,  cudaFuncAttributeMaxDynamicSharedMemorySize, SMEM_ATTN);

    transpose_w_kernel<<<4, 256>>>((const float*)d_in[1], (const float*)d_in[3],
                                   (const float*)d_in[5], (const float*)d_in[7]);
    split_x_kernel<<<ROWS*DIM/4/256, 256>>>(x);
    qkv_wmma_kernel<<<dim3(ROWS/64, 3), 256, SMEM_QKV>>>(bq, bk, bv);
    attn_mma_kernel<<<dim3(SEQ/128, BATCH), 256, SMEM_ATTN>>>();
    proj_wmma_kernel<<<ROWS/64, 256, SMEM_QKV>>>(bo, gamma, beta, out);
}

// round 17
// speedup vs baseline: 1.6820x; 1.0774x over previous
#include <cuda_runtime.h>
#include <cuda_bf16.h>
#include <mma.h>
#include <math.h>
#include <stdint.h>
using namespace nvcuda;

#define BATCH 8
#define SEQ   2048
#define DIM   256
#define ROWS  (BATCH*SEQ)
#define LOG2E 1.4426950408889634f

__device__ __align__(16) __nv_bfloat16 g_WTh[4*DIM*DIM], g_WTl[4*DIM*DIM];
__device__ __align__(16) __nv_bfloat16 g_Qh[ROWS*DIM], g_Ql[ROWS*DIM];
__device__ __align__(16) __nv_bfloat16 g_Kh[ROWS*DIM], g_Kl[ROWS*DIM];
__device__ __align__(16) __nv_bfloat16 g_Vh[ROWS*DIM], g_Vl[ROWS*DIM];
__device__ __align__(16) __nv_bfloat16 g_LOCh[ROWS*DIM], g_LOCl[ROWS*DIM];

__device__ __forceinline__ float fexp2(float x){ float y; asm("ex2.approx.ftz.f32 %0, %1;" : "=f"(y) : "f"(x)); return y; }

__device__ __forceinline__ uint32_t packbf(__nv_bfloat16 a, __nv_bfloat16 b){
    return (uint32_t)__bfloat16_as_ushort(a) | ((uint32_t)__bfloat16_as_ushort(b)<<16);
}
__device__ __forceinline__ void split4(float4 v, uint2& h, uint2& l){
    __nv_bfloat16 hx=__float2bfloat16(v.x), hy=__float2bfloat16(v.y), hz=__float2bfloat16(v.z), hw=__float2bfloat16(v.w);
    h.x = packbf(hx,hy); h.y = packbf(hz,hw);
    l.x = packbf(__float2bfloat16(v.x-__bfloat162float(hx)), __float2bfloat16(v.y-__bfloat162float(hy)));
    l.y = packbf(__float2bfloat16(v.z-__bfloat162float(hz)), __float2bfloat16(v.w-__bfloat162float(hw)));
}
__device__ __forceinline__ void cp16(void* s, const void* g){
    uint32_t a = (uint32_t)__cvta_generic_to_shared(s);
    asm volatile("cp.async.cg.shared.global [%0], [%1], 16;" :: "r"(a), "l"(g) : "memory");
}
#define CP_COMMIT() asm volatile("cp.async.commit_group;" ::: "memory")
#define CP_WAIT1()  asm volatile("cp.async.wait_group 1;" ::: "memory")

__device__ __forceinline__ void ldsm4(uint32_t* r, uint32_t addr){
    asm volatile("ldmatrix.sync.aligned.m8n8.x4.shared.b16 {%0,%1,%2,%3}, [%4];"
        : "=r"(r[0]),"=r"(r[1]),"=r"(r[2]),"=r"(r[3]) : "r"(addr));
}
__device__ __forceinline__ void ldsm4t(uint32_t* r, uint32_t addr){
    asm volatile("ldmatrix.sync.aligned.m8n8.x4.trans.shared.b16 {%0,%1,%2,%3}, [%4];"
        : "=r"(r[0]),"=r"(r[1]),"=r"(r[2]),"=r"(r[3]) : "r"(addr));
}
__device__ __forceinline__ void mma16816(float* c, const uint32_t* a, const uint32_t* b){
    asm volatile("mma.sync.aligned.m16n8k16.row.col.f32.bf16.bf16.f32 "
        "{%0,%1,%2,%3}, {%4,%5,%6,%7}, {%8,%9}, {%0,%1,%2,%3};"
        : "+f"(c[0]),"+f"(c[1]),"+f"(c[2]),"+f"(c[3])
        : "r"(a[0]),"r"(a[1]),"r"(a[2]),"r"(a[3]), "r"(b[0]),"r"(b[1]));
}

// ---------------- weight transpose + hi/lo split ----------------
__global__ void transpose_w_kernel(const float* __restrict__ Wq, const float* __restrict__ Wk,
                                   const float* __restrict__ Wv, const float* __restrict__ Wo){
    int m = blockIdx.x;
    const float* W = (m==0)?Wq:((m==1)?Wk:((m==2)?Wv:Wo));
    __nv_bfloat16* WTh = g_WTh + (size_t)m*DIM*DIM;
    __nv_bfloat16* WTl = g_WTl + (size_t)m*DIM*DIM;
    for (int idx = threadIdx.x; idx < DIM*DIM; idx += blockDim.x){
        float w = W[(idx&255)*DIM + (idx>>8)];
        __nv_bfloat16 h = __float2bfloat16(w);
        WTh[idx] = h;
        WTl[idx] = __float2bfloat16(w - __bfloat162float(h));
    }
}

// ---------------- WMMA bf16-split 64x256 GEMM: 2m x 4n warp grid ----------------
#define XS 72
#define WS 264
#define QK_XH 0
#define QK_XL 9216
#define QK_W  18432
#define QK_WL (QK_W + 33792)
#define SMEM_QKV (QK_W + 67584)

// mainloop body after X tiles staged (expects Wh/Wl staged too); mw in {0,1}, np in {0..3}
#define GEMM_CK_MMA(Xh, Xl, Wh, Wl, mw, np, acc)                                          \
    _Pragma("unroll")                                                                     \
    for (int k=0;k<4;++k){                                                                \
        wmma::fragment<wmma::matrix_a,16,16,16,__nv_bfloat16,wmma::row_major> ah[2], al[2];\
        _Pragma("unroll")                                                                 \
        for (int i=0;i<2;++i){                                                            \
            wmma::load_matrix_sync(ah[i], (Xh) + ((mw)*32+i*16)*XS + k*16, XS);           \
            wmma::load_matrix_sync(al[i], (Xl) + ((mw)*32+i*16)*XS + k*16, XS);           \
        }                                                                                 \
        _Pragma("unroll")                                                                 \
        for (int j=0;j<4;++j){                                                            \
            int n0 = (np)*64 + j*16;                                                      \
            wmma::fragment<wmma::matrix_b,16,16,16,__nv_bfloat16,wmma::row_major> bh, bl; \
            wmma::load_matrix_sync(bh, (Wh) + k*16*WS + n0, WS);                          \
            wmma::load_matrix_sync(bl, (Wl) + k*16*WS + n0, WS);                          \
            _Pragma("unroll")                                                             \
            for (int i=0;i<2;++i){                                                        \
                wmma::mma_sync(acc[i][j], ah[i], bh, acc[i][j]);                          \
                wmma::mma_sync(acc[i][j], al[i], bh, acc[i][j]);                          \
                wmma::mma_sync(acc[i][j], ah[i], bl, acc[i][j]);                          \
            }                                                                             \
        }                                                                                 \
    }

// ---------------- QKV projections (x split inline) ----------------
__global__ void __launch_bounds__(256,2) qkv_wmma_kernel(const float* __restrict__ x,
        const float* __restrict__ bq, const float* __restrict__ bk, const float* __restrict__ bv){
    extern __shared__ char smch[];
    __nv_bfloat16* Xh = (__nv_bfloat16*)(smch+QK_XH);
    __nv_bfloat16* Xl = (__nv_bfloat16*)(smch+QK_XL);
    __nv_bfloat16* Wh = (__nv_bfloat16*)(smch+QK_W);
    __nv_bfloat16* Wl = (__nv_bfloat16*)(smch+QK_WL);
    float* Of = (float*)(smch+QK_W);
    int tid = threadIdx.x, wid = tid>>5;
    int m = blockIdx.y, r0 = blockIdx.x*64;
    int mw = wid&1, np = wid>>1;
    const __nv_bfloat16* WTh = g_WTh + (size_t)m*DIM*DIM;
    const __nv_bfloat16* WTl = g_WTl + (size_t)m*DIM*DIM;

    wmma::fragment<wmma::accumulator,16,16,16,float> acc[2][4];
    #pragma unroll
    for (int i=0;i<2;i++)
        #pragma unroll
        for (int j=0;j<4;j++) wmma::fill_fragment(acc[i][j], 0.f);

    for (int ck = 0; ck < 4; ++ck){
        __syncthreads();
        // stage X [64 x 64] from fp32 with inline hi/lo split
        #pragma unroll
        for (int it=0; it<4; ++it){
            int idx = tid + it*256;           // 0..1023 = 64 rows x 16 float4
            int r = idx>>4, c4 = idx&15;
            float4 v = *(const float4*)(x + (size_t)(r0+r)*DIM + ck*64 + c4*4);
            uint2 h,l; split4(v,h,l);
            *(uint2*)(Xh + r*XS + c4*4) = h;
            *(uint2*)(Xl + r*XS + c4*4) = l;
        }
        // stage W chunk [64 x 256]
        #pragma unroll
        for (int it=0; it<8; ++it){
            int idx = tid + it*256;
            int dd = idx>>5, c8 = idx&31;
            size_t gsrc = (size_t)(ck*64+dd)*DIM + c8*8;
            *(uint4*)(Wh + dd*WS + c8*8) = *(const uint4*)(WTh + gsrc);
            *(uint4*)(Wl + dd*WS + c8*8) = *(const uint4*)(WTl + gsrc);
        }
        __syncthreads();
        GEMM_CK_MMA(Xh, Xl, Wh, Wl, mw, np, acc)
    }
    __syncthreads();
    #pragma unroll
    for (int i=0;i<2;++i)
        #pragma unroll
        for (int j=0;j<4;++j)
            wmma::store_matrix_sync(Of + (mw*32+i*16)*WS + np*64 + j*16, acc[i][j], WS, wmma::mem_row_major);
    __syncthreads();

    const float* bias = (m==0)?bq:((m==1)?bk:bv);
    __nv_bfloat16* oh = (m==0)?g_Qh:((m==1)?g_Kh:g_Vh);
    __nv_bfloat16* ol = (m==0)?g_Ql:((m==1)?g_Kl:g_Vl);
    int row = tid>>2, part = tid&3;
    #pragma unroll
    for (int c4=0;c4<16;++c4){
        float4 v = *(const float4*)(Of + row*WS + part*64 + c4*4);
        float4 bb = *(const float4*)(bias + part*64 + c4*4);
        v.x+=bb.x; v.y+=bb.y; v.z+=bb.z; v.w+=bb.w;
        uint2 h,l; split4(v,h,l);
        size_t off = (size_t)(r0+row)*DIM + part*64 + c4*4;
        *(uint2*)(oh+off) = h; *(uint2*)(ol+off) = l;
    }
}

// ---------------- raw-mma flash attention: 32-key macro-iters, Q amortized ----------------
#define AQH 0
#define AQL 67584
#define AKV 135168
#define KVB 8448                 // one 16x264 bf16 buffer
#define SMEM_ATTN (AKV + 8*KVB)  // 202752

__device__ __forceinline__ void stageK(char* sm, size_t bb, int kt, int sel, int tid){
    size_t gsrc = bb + (size_t)kt*16*DIM;
    #pragma unroll
    for (int it=0; it<2; ++it){
        int idx = tid + it*256;
        int r = idx>>5, c8 = idx&31;
        int so = r*528 + c8*16;
        size_t go = gsrc + (size_t)r*DIM + c8*8;
        cp16(sm + AKV + sel*KVB + so,     g_Kh + go);
        cp16(sm + AKV + (2+sel)*KVB + so, g_Kl + go);
    }
}
__device__ __forceinline__ void stageV(char* sm, size_t bb, int kt, int sel, int tid){
    size_t gsrc = bb + (size_t)kt*16*DIM;
    #pragma unroll
    for (int it=0; it<2; ++it){
        int idx = tid + it*256;
        int r = idx>>5, c8 = idx&31;
        int so = r*528 + c8*16;
        size_t go = gsrc + (size_t)r*DIM + c8*8;
        cp16(sm + AKV + (4+sel)*KVB + so, g_Vh + go);
        cp16(sm + AKV + (6+sel)*KVB + so, g_Vl + go);
    }
}

__global__ void __launch_bounds__(256,1) attn_mma_kernel(){
    extern __shared__ char sm[];
    const uint32_t sbase = (uint32_t)__cvta_generic_to_shared(sm);
    int tid = threadIdx.x, wid = tid>>5, L = tid&31;
    int b = blockIdx.y, q0 = blockIdx.x*128;
    size_t bb = (size_t)b*SEQ*DIM;

    stageK(sm, bb, 0, 0, tid); stageK(sm, bb, 1, 1, tid); CP_COMMIT();
    stageV(sm, bb, 0, 0, tid); stageV(sm, bb, 1, 1, tid); CP_COMMIT();

    #pragma unroll
    for (int it=0; it<16; ++it){
        int idx = tid + it*256;
        int r = idx>>5, c8 = idx&31;
        size_t go = bb + (size_t)(q0+r)*DIM + c8*8;
        *(uint4*)(sm + AQH + r*528 + c8*16) = *(const uint4*)(g_Qh + go);
        *(uint4*)(sm + AQL + r*528 + c8*16) = *(const uint4*)(g_Ql + go);
    }

    uint32_t qhB = sbase + AQH + (uint32_t)((wid*16 + (L&15))*528 + (L>>4)*16);
    uint32_t qlB = qhB + (AQL - AQH);
    uint32_t kOff = (uint32_t)(((L&7) + ((L>>4)<<3))*528 + ((L>>3)&1)*16);
    uint32_t vOff = (uint32_t)((L&15)*528 + (L>>4)*16);
    const uint32_t kB0  = sbase + AKV + kOff,         kB0l = kB0 + 2*KVB;
    const uint32_t kB1  = kB0 + KVB,                  kB1l = kB0 + 3*KVB;
    const uint32_t vB0  = sbase + AKV + 4*KVB + vOff, vB0l = vB0 + 2*KVB;
    const uint32_t vB1  = vB0 + KVB,                  vB1l = vB0 + 3*KVB;

    float o[32][4];
    #pragma unroll
    for (int j=0;j<32;++j){ o[j][0]=0.f; o[j][1]=0.f; o[j][2]=0.f; o[j][3]=0.f; }
    float ps0 = 0.f, ps1 = 0.f;

    CP_WAIT1();
    __syncthreads();

    const int NMI = SEQ/32;
    for (int mi = 0; mi < NMI; ++mi){
        float sA[4][4], sB[4][4];
        #pragma unroll
        for (int q=0;q<4;++q){
            sA[q][0]=sA[q][1]=sA[q][2]=sA[q][3]=0.f;
            sB[q][0]=sB[q][1]=sB[q][2]=sB[q][3]=0.f;
        }
        #pragma unroll
        for (int kd=0; kd<16; ++kd){
            uint32_t ah[4], al[4], b0h[4], b0l[4], b1h[4], b1l[4];
            ldsm4(ah, qhB + kd*32);
            ldsm4(al, qlB + kd*32);
            ldsm4(b0h, kB0  + kd*32);
            ldsm4(b0l, kB0l + kd*32);
            ldsm4(b1h, kB1  + kd*32);
            ldsm4(b1l, kB1l + kd*32);
            mma16816(sA[0], ah, b0h+0); mma16816(sA[1], ah, b0h+2);
            mma16816(sA[2], ah, b1h+0); mma16816(sA[3], ah, b1h+2);
            mma16816(sB[0], al, b0h+0); mma16816(sB[1], al, b0h+2);
            mma16816(sB[2], al, b1h+0); mma16816(sB[3], al, b1h+2);
            mma16816(sA[0], ah, b0l+0); mma16816(sA[1], ah, b0l+2);
            mma16816(sA[2], ah, b1l+0); mma16816(sA[3], ah, b1l+2);
        }

        float p[16];
        #pragma unroll
        for (int blk=0; blk<4; ++blk)
            #pragma unroll
            for (int e=0; e<4; ++e)
                p[blk*4+e] = fexp2((sA[blk][e] + sB[blk][e])*LOG2E);
        #pragma unroll
        for (int blk=0; blk<4; ++blk){
            ps0 += p[blk*4+0] + p[blk*4+1];
            ps1 += p[blk*4+2] + p[blk*4+3];
        }
        uint32_t a0h[4], a0l[4], a1h[4], a1l[4];
        #pragma unroll
        for (int q=0; q<4; ++q){
            float pa = p[2*q], pb = p[2*q+1];
            __nv_bfloat16 ha = __float2bfloat16(pa), hb = __float2bfloat16(pb);
            a0h[q] = packbf(ha, hb);
            a0l[q] = packbf(__float2bfloat16(pa-__bfloat162float(ha)),
                            __float2bfloat16(pb-__bfloat162float(hb)));
            float pc = p[8+2*q], pd = p[9+2*q];
            __nv_bfloat16 hc = __float2bfloat16(pc), hd = __float2bfloat16(pd);
            a1h[q] = packbf(hc, hd);
            a1l[q] = packbf(__float2bfloat16(pc-__bfloat162float(hc)),
                            __float2bfloat16(pd-__bfloat162float(hd)));
        }

        __syncthreads();
        int t2 = mi*2 + 2;
        if (t2 < SEQ/16){ stageK(sm, bb, t2, 0, tid); stageK(sm, bb, t2+1, 1, tid); }
        CP_COMMIT();
        CP_WAIT1();
        __syncthreads();

        #pragma unroll
        for (int j=0; j<16; ++j){
            uint32_t b0h[4], b0l[4], b1h[4], b1l[4];
            ldsm4t(b0h, vB0  + j*32);
            ldsm4t(b0l, vB0l + j*32);
            ldsm4t(b1h, vB1  + j*32);
            ldsm4t(b1l, vB1l + j*32);
            mma16816(o[2*j],   a0h, b0h+0); mma16816(o[2*j+1], a0h, b0h+2);
            mma16816(o[2*j],   a0l, b0h+0); mma16816(o[2*j+1], a0l, b0h+2);
            mma16816(o[2*j],   a0h, b0l+0); mma16816(o[2*j+1], a0h, b0l+2);
            mma16816(o[2*j],   a1h, b1h+0); mma16816(o[2*j+1], a1h, b1h+2);
            mma16816(o[2*j],   a1l, b1h+0); mma16816(o[2*j+1], a1l, b1h+2);
            mma16816(o[2*j],   a1h, b1l+0); mma16816(o[2*j+1], a1h, b1l+2);
        }

        __syncthreads();
        if (t2 < SEQ/16){ stageV(sm, bb, t2, 0, tid); stageV(sm, bb, t2+1, 1, tid); }
        CP_COMMIT();
        CP_WAIT1();
        __syncthreads();
    }

    ps0 += __shfl_xor_sync(0xffffffffu, ps0, 1);
    ps0 += __shfl_xor_sync(0xffffffffu, ps0, 2);
    ps1 += __shfl_xor_sync(0xffffffffu, ps1, 1);
    ps1 += __shfl_xor_sync(0xffffffffu, ps1, 2);
    float inv0 = 1.0f/ps0, inv1 = 1.0f/ps1;
    int g = L>>2, t = L&3;
    size_t r0o = (size_t)(b*SEQ + q0 + wid*16 + g)*DIM;
    size_t r1o = r0o + (size_t)8*DIM;
    #pragma unroll
    for (int j=0; j<32; ++j){
        int col = j*8 + 2*t;
        float v0 = o[j][0]*inv0, v1 = o[j][1]*inv0;
        float v2 = o[j][2]*inv1, v3 = o[j][3]*inv1;
        __nv_bfloat16 h0=__float2bfloat16(v0), h1=__float2bfloat16(v1);
        __nv_bfloat16 h2=__float2bfloat16(v2), h3=__float2bfloat16(v3);
        *(uint32_t*)(g_LOCh + r0o + col) = packbf(h0,h1);
        *(uint32_t*)(g_LOCl + r0o + col) = packbf(__float2bfloat16(v0-__bfloat162float(h0)),
                                                  __float2bfloat16(v1-__bfloat162float(h1)));
        *(uint32_t*)(g_LOCh + r1o + col) = packbf(h2,h3);
        *(uint32_t*)(g_LOCl + r1o + col) = packbf(__float2bfloat16(v2-__bfloat162float(h2)),
                                                  __float2bfloat16(v3-__bfloat162float(h3)));
    }
}

// ---------------- output projection (WMMA 2m x 4n) + LayerNorm + LeakyReLU ----------------
__global__ void __launch_bounds__(256,2) proj_wmma_kernel(
        const float* __restrict__ bo, const float* __restrict__ gamma,
        const float* __restrict__ beta, float* __restrict__ out){
    extern __shared__ char smch[];
    __nv_bfloat16* Xh = (__nv_bfloat16*)(smch+QK_XH);
    __nv_bfloat16* Xl = (__nv_bfloat16*)(smch+QK_XL);
    __nv_bfloat16* Wh = (__nv_bfloat16*)(smch+QK_W);
    __nv_bfloat16* Wl = (__nv_bfloat16*)(smch+QK_WL);
    float* Of = (float*)(smch+QK_W);
    int tid = threadIdx.x, wid = tid>>5;
    int r0 = blockIdx.x*64;
    int mw = wid&1, np = wid>>1;
    const __nv_bfloat16* WTh = g_WTh + (size_t)3*DIM*DIM;
    const __nv_bfloat16* WTl = g_WTl + (size_t)3*DIM*DIM;

    wmma::fragment<wmma::accumulator,16,16,16,float> acc[2][4];
    #pragma unroll
    for (int i=0;i<2;i++)
        #pragma unroll
        for (int j=0;j<4;j++) wmma::fill_fragment(acc[i][j], 0.f);

    for (int ck = 0; ck < 4; ++ck){
        __syncthreads();
        #pragma unroll
        for (int it=0; it<2; ++it){
            int idx = tid + it*256;
            int r = idx>>3, c8 = idx&7;
            size_t gsrc = (size_t)(r0+r)*DIM + ck*64 + c8*8;
            *(uint4*)(Xh + r*XS + c8*8) = *(const uint4*)(g_LOCh + gsrc);
            *(uint4*)(Xl + r*XS + c8*8) = *(const uint4*)(g_LOCl + gsrc);
        }
        #pragma unroll
        for (int it=0; it<8; ++it){
            int idx = tid + it*256;
            int dd = idx>>5, c8 = idx&31;
            size_t gsrc = (size_t)(ck*64+dd)*DIM + c8*8;
            *(uint4*)(Wh + dd*WS + c8*8) = *(const uint4*)(WTh + gsrc);
            *(uint4*)(Wl + dd*WS + c8*8) = *(const uint4*)(WTl + gsrc);
        }
        __syncthreads();
        GEMM_CK_MMA(Xh, Xl, Wh, Wl, mw, np, acc)
    }
    __syncthreads();
    #pragma unroll
    for (int i=0;i<2;++i)
        #pragma unroll
        for (int j=0;j<4;++j)
            wmma::store_matrix_sync(Of + (mw*32+i*16)*WS + np*64 + j*16, acc[i][j], WS, wmma::mem_row_major);
    __syncthreads();

    int row = tid>>2, part = tid&3;
    float* myrow = Of + row*WS + part*64;

    #pragma unroll
    for (int c4=0;c4<16;++c4){
        float4 v = *(const float4*)(myrow + c4*4);
        float4 bb = *(const float4*)(bo + part*64 + c4*4);
        v.x+=bb.x; v.y+=bb.y; v.z+=bb.z; v.w+=bb.w;
        *(float4*)(myrow + c4*4) = v;
    }

    float ssum = 0.f;
    #pragma unroll
    for (int c4=0;c4<16;++c4){
        float4 v = *(const float4*)(myrow + c4*4);
        ssum += (v.x+v.y)+(v.z+v.w);
    }
    ssum += __shfl_xor_sync(0xffffffffu, ssum, 1);
    ssum += __shfl_xor_sync(0xffffffffu, ssum, 2);
    float mu = ssum * (1.0f/DIM);

    float vsum = 0.f;
    #pragma unroll
    for (int c4=0;c4<16;++c4){
        float4 v = *(const float4*)(myrow + c4*4);
        float dx=v.x-mu, dy=v.y-mu, dz=v.z-mu, dw=v.w-mu;
        vsum += (dx*dx+dy*dy)+(dz*dz+dw*dw);
    }
    vsum += __shfl_xor_sync(0xffffffffu, vsum, 1);
    vsum += __shfl_xor_sync(0xffffffffu, vsum, 2);
    float rstd = rsqrtf(vsum*(1.0f/DIM) + 1e-5f);

    float* gout = out + (size_t)(r0+row)*DIM + part*64;
    #pragma unroll
    for (int c4=0;c4<16;++c4){
        float4 h = *(const float4*)(myrow + c4*4);
        float4 g4 = *(const float4*)(gamma + part*64 + c4*4);
        float4 bt = *(const float4*)(beta  + part*64 + c4*4);
        float4 y;
        y.x=(h.x-mu)*rstd*g4.x+bt.x; y.x=(y.x>=0.f)?y.x:0.01f*y.x;
        y.y=(h.y-mu)*rstd*g4.y+bt.y; y.y=(y.y>=0.f)?y.y:0.01f*y.y;
        y.z=(h.z-mu)*rstd*g4.z+bt.z; y.z=(y.z>=0.f)?y.z:0.01f*y.z;
        y.w=(h.w-mu)*rstd*g4.w+bt.w; y.w=(y.w>=0.f)?y.w:0.01f*y.w;
        *(float4*)(gout + c4*4) = y;
    }
}

// ---------------- entry ----------------
extern "C" void kernel_launch(void* const* d_in, const int* in_sizes, int n_in,
                              void* d_out, int out_size){
    const float* x     = (const float*)d_in[0];
    const float* bq    = (const float*)d_in[2];
    const float* bk    = (const float*)d_in[4];
    const float* bv    = (const float*)d_in[6];
    const float* bo    = (const float*)d_in[8];
    const float* gamma = (const float*)d_in[9];
    const float* beta  = (const float*)d_in[10];
    float* out = (float*)d_out;

    cudaFuncSetAttribute(qkv_wmma_kernel,  cudaFuncAttributeMaxDynamicSharedMemorySize, SMEM_QKV);
    cudaFuncSetAttribute(proj_wmma_kernel, cudaFuncAttributeMaxDynamicSharedMemorySize, SMEM_QKV);
    cudaFuncSetAttribute(attn_mma_kernel,  cudaFuncAttributeMaxDynamicSharedMemorySize, SMEM_ATTN);

    transpose_w_kernel<<<4, 256>>>((const float*)d_in[1], (const float*)d_in[3],
                                   (const float*)d_in[5], (const float*)d_in[7]);
    qkv_wmma_kernel<<<dim3(ROWS/64, 3), 256, SMEM_QKV>>>(x, bq, bk, bv);
    attn_mma_kernel<<<dim3(SEQ/128, BATCH), 256, SMEM_ATTN>>>();
    proj_wmma_kernel<<<ROWS/64, 256, SMEM_QKV>>>(bo, gamma, beta, out);
}